// round 1
// baseline (speedup 1.0000x reference)
#include <cuda_runtime.h>
#include <math.h>

// Problem constants
#define T_TOK 12000          // B*S/K tokens
#define D_IN  2560           // ENC*K
#define HID   512
#define LLM   2048
#define NE    8
#define NTOP  2
#define TWO   (T_TOK*NTOP)   // 24000 (token,slot) pairs

// ---------------- static device scratch (allowed; no runtime alloc) -------
__device__ float g_nx[(size_t)T_TOK * D_IN];      // LN'd input      ~123 MB
__device__ float g_act[(size_t)T_TOK * HID];      // shared swiglu   ~25 MB
__device__ float g_shared[(size_t)T_TOK * LLM];   // shared output   ~98 MB
__device__ float g_eact[(size_t)TWO * HID];       // expert swiglu   ~49 MB
__device__ float g_eo[(size_t)TWO * LLM];         // expert outputs ~197 MB
__device__ int   g_idx[TWO];
__device__ float g_w[TWO];
__device__ int   g_perm[TWO];
__device__ float g_permw[TWO];
__device__ int   g_pos[TWO];
__device__ int   g_cnt[NE];
__device__ int   g_off[NE + 1];
__device__ int   g_cur[NE];

// ---------------- helpers --------------------------------------------------
__device__ __forceinline__ void blockReduce2(float& sum, float& sq) {
    __shared__ float ss[8], sv[8];
    #pragma unroll
    for (int o = 16; o > 0; o >>= 1) {
        sum += __shfl_down_sync(0xFFFFFFFFu, sum, o);
        sq  += __shfl_down_sync(0xFFFFFFFFu, sq,  o);
    }
    int w = threadIdx.x >> 5, l = threadIdx.x & 31;
    if (l == 0) { ss[w] = sum; sv[w] = sq; }
    __syncthreads();
    if (w == 0) {
        sum = (l < 8) ? ss[l] : 0.f;
        sq  = (l < 8) ? sv[l] : 0.f;
        #pragma unroll
        for (int o = 4; o > 0; o >>= 1) {
            sum += __shfl_down_sync(0xFFFFFFFFu, sum, o);
            sq  += __shfl_down_sync(0xFFFFFFFFu, sq,  o);
        }
        if (l == 0) { ss[0] = sum; sv[0] = sq; }
    }
    __syncthreads();
    sum = ss[0]; sq = sv[0];
}

// ---------------- kernel 0: zero counters ----------------------------------
__global__ void init_kernel() {
    int i = threadIdx.x;
    if (i < NE) { g_cnt[i] = 0; g_cur[i] = 0; }
}

// ---------------- kernel 1: LN_pre fused with router/top2 ------------------
__global__ __launch_bounds__(256) void ln_router_kernel(
    const float* __restrict__ x,
    const float* __restrict__ lng, const float* __restrict__ lnb,
    const float* __restrict__ rw,  const float* __restrict__ rb)
{
    int t = blockIdx.x;
    const float* xr = x + (size_t)t * D_IN;
    __shared__ float s_nx[D_IN];
    __shared__ float s_logit[NE];
    int tid = threadIdx.x;

    float v[10];
    float sum = 0.f, sq = 0.f;
    #pragma unroll
    for (int i = 0; i < 10; i++) {
        v[i] = xr[tid + i * 256];
        sum += v[i]; sq += v[i] * v[i];
    }
    blockReduce2(sum, sq);
    float m = sum * (1.f / D_IN);
    float var = sq * (1.f / D_IN) - m * m;
    float rinv = rsqrtf(var + 1e-6f);
    float* nxr = g_nx + (size_t)t * D_IN;
    #pragma unroll
    for (int i = 0; i < 10; i++) {
        int j = tid + i * 256;
        float nv = (v[i] - m) * rinv * lng[j] + lnb[j];
        s_nx[j] = nv;
        nxr[j] = nv;
    }
    __syncthreads();

    // router: warp w computes logit w
    int w = tid >> 5, lane = tid & 31;
    float acc = 0.f;
    const float* rwr = rw + (size_t)w * D_IN;
    for (int i = lane; i < D_IN; i += 32) acc += s_nx[i] * rwr[i];
    #pragma unroll
    for (int o = 16; o > 0; o >>= 1) acc += __shfl_down_sync(0xFFFFFFFFu, acc, o);
    if (lane == 0) s_logit[w] = acc + rb[w];
    __syncthreads();

    if (tid == 0) {
        float mx = s_logit[0];
        #pragma unroll
        for (int e = 1; e < NE; e++) mx = fmaxf(mx, s_logit[e]);
        float p[NE], se = 0.f;
        #pragma unroll
        for (int e = 0; e < NE; e++) { p[e] = __expf(s_logit[e] - mx); se += p[e]; }
        float rse = 1.f / se;
        #pragma unroll
        for (int e = 0; e < NE; e++) p[e] *= rse;
        int i0 = 0;
        #pragma unroll
        for (int e = 1; e < NE; e++) if (p[e] > p[i0]) i0 = e;
        int i1 = (i0 == 0) ? 1 : 0;
        #pragma unroll
        for (int e = 0; e < NE; e++) if (e != i0 && p[e] > p[i1]) i1 = e;
        float s2 = p[i0] + p[i1] + 1e-20f;
        g_idx[2 * t + 0] = i0; g_w[2 * t + 0] = p[i0] / s2;
        g_idx[2 * t + 1] = i1; g_w[2 * t + 1] = p[i1] / s2;
        atomicAdd(&g_cnt[i0], 1);
        atomicAdd(&g_cnt[i1], 1);
    }
}

// ---------------- kernel 2: prefix sum of expert counts --------------------
__global__ void scan_kernel() {
    if (threadIdx.x == 0) {
        int o = 0;
        for (int e = 0; e < NE; e++) { g_off[e] = o; o += g_cnt[e]; }
        g_off[NE] = o;
    }
}

// ---------------- kernel 3: build expert-sorted permutation ----------------
__global__ void build_kernel() {
    int t = blockIdx.x * blockDim.x + threadIdx.x;
    if (t >= T_TOK) return;
    #pragma unroll
    for (int k = 0; k < NTOP; k++) {
        int e = g_idx[2 * t + k];
        int p = g_off[e] + atomicAdd(&g_cur[e], 1);
        g_perm[p]  = t;
        g_permw[p] = g_w[2 * t + k];
        g_pos[2 * t + k] = p;
    }
}

// ---------------- kernel 4: GEMM w12 + SwiGLU (shared / experts) -----------
// act[r, c] = silu(nx[r,:]·w12[c,:]) * (nx[r,:]·w12[H+c,:])
// BM=128 rows, BN=64 act-cols (128 w12 rows), BK=32
__global__ __launch_bounds__(256, 2) void gemm12_kernel(
    const float* __restrict__ Wbase, int useGather)
{
    const int BM = 128, BN = 64, BK = 32;
    int rowStart, nrows;
    const float* W;
    if (useGather) {
        int e = blockIdx.z;
        rowStart = g_off[e] + blockIdx.y * BM;
        int rowEnd = g_off[e + 1];
        if (rowStart >= rowEnd) return;
        nrows = min(BM, rowEnd - rowStart);
        W = Wbase + (size_t)e * (2 * HID) * D_IN;
    } else {
        rowStart = blockIdx.y * BM;
        if (rowStart >= T_TOK) return;
        nrows = min(BM, T_TOK - rowStart);
        W = Wbase;
    }
    int colBase = blockIdx.x * BN;

    __shared__ __align__(16) float As[BK][132];
    __shared__ __align__(16) float Bs[BK][132];
    float acc_g[8][4] = {}, acc_v[8][4] = {};
    int tid = threadIdx.x;
    int tx = tid & 15, ty = tid >> 4;

    for (int k0 = 0; k0 < D_IN; k0 += BK) {
        #pragma unroll
        for (int i = 0; i < 4; i++) {
            int f = tid + i * 256;
            int r = f >> 3;
            int kq = (f & 7) * 4;
            float4 va = make_float4(0.f, 0.f, 0.f, 0.f);
            if (r < nrows) {
                int gr = rowStart + r;
                int arow = useGather ? g_perm[gr] : gr;
                va = *(const float4*)(g_nx + (size_t)arow * D_IN + k0 + kq);
            }
            As[kq + 0][r] = va.x; As[kq + 1][r] = va.y;
            As[kq + 2][r] = va.z; As[kq + 3][r] = va.w;
        }
        #pragma unroll
        for (int i = 0; i < 4; i++) {
            int f = tid + i * 256;
            int r = f >> 3;
            int kq = (f & 7) * 4;
            int wrow = (r < 64) ? (colBase + r) : (HID + colBase + (r - 64));
            float4 vb = *(const float4*)(W + (size_t)wrow * D_IN + k0 + kq);
            Bs[kq + 0][r] = vb.x; Bs[kq + 1][r] = vb.y;
            Bs[kq + 2][r] = vb.z; Bs[kq + 3][r] = vb.w;
        }
        __syncthreads();
        #pragma unroll
        for (int k = 0; k < BK; k++) {
            float a[8], bg[4], bv[4];
            *(float4*)(a)     = *(const float4*)&As[k][ty * 8];
            *(float4*)(a + 4) = *(const float4*)&As[k][ty * 8 + 4];
            *(float4*)(bg)    = *(const float4*)&Bs[k][tx * 4];
            *(float4*)(bv)    = *(const float4*)&Bs[k][64 + tx * 4];
            #pragma unroll
            for (int i = 0; i < 8; i++)
                #pragma unroll
                for (int j = 0; j < 4; j++) {
                    acc_g[i][j] += a[i] * bg[j];
                    acc_v[i][j] += a[i] * bv[j];
                }
        }
        __syncthreads();
    }
    float* Out = useGather ? g_eact : g_act;
    #pragma unroll
    for (int i = 0; i < 8; i++) {
        int r = ty * 8 + i;
        if (r < nrows) {
            int orow = rowStart + r;
            #pragma unroll
            for (int j = 0; j < 4; j++) {
                float gv = acc_g[i][j];
                float s = gv / (1.f + __expf(-gv));
                Out[(size_t)orow * HID + colBase + tx * 4 + j] = s * acc_v[i][j];
            }
        }
    }
}

// ---------------- kernel 5: GEMM w3 (shared / experts, fused slot weight) --
// out[r, c] = scale(r) * (act[r,:]·w3[c,:]) ; K = 512
__global__ __launch_bounds__(256, 2) void gemm3_kernel(
    const float* __restrict__ Wbase, int useExpert)
{
    const int BM = 128, BN = 128, BK = 32;
    int rowStart, nrows;
    const float* W;
    if (useExpert) {
        int e = blockIdx.z;
        rowStart = g_off[e] + blockIdx.y * BM;
        int rowEnd = g_off[e + 1];
        if (rowStart >= rowEnd) return;
        nrows = min(BM, rowEnd - rowStart);
        W = Wbase + (size_t)e * LLM * HID;
    } else {
        rowStart = blockIdx.y * BM;
        if (rowStart >= T_TOK) return;
        nrows = min(BM, T_TOK - rowStart);
        W = Wbase;
    }
    int colBase = blockIdx.x * BN;
    const float* Act = useExpert ? g_eact : g_act;

    __shared__ __align__(16) float As[BK][132];
    __shared__ __align__(16) float Bs[BK][132];
    float acc[8][8] = {};
    int tid = threadIdx.x;
    int tx = tid & 15, ty = tid >> 4;

    for (int k0 = 0; k0 < HID; k0 += BK) {
        #pragma unroll
        for (int i = 0; i < 4; i++) {
            int f = tid + i * 256;
            int r = f >> 3;
            int kq = (f & 7) * 4;
            float4 va = make_float4(0.f, 0.f, 0.f, 0.f);
            if (r < nrows)
                va = *(const float4*)(Act + (size_t)(rowStart + r) * HID + k0 + kq);
            As[kq + 0][r] = va.x; As[kq + 1][r] = va.y;
            As[kq + 2][r] = va.z; As[kq + 3][r] = va.w;
        }
        #pragma unroll
        for (int i = 0; i < 4; i++) {
            int f = tid + i * 256;
            int r = f >> 3;
            int kq = (f & 7) * 4;
            float4 vb = *(const float4*)(W + (size_t)(colBase + r) * HID + k0 + kq);
            Bs[kq + 0][r] = vb.x; Bs[kq + 1][r] = vb.y;
            Bs[kq + 2][r] = vb.z; Bs[kq + 3][r] = vb.w;
        }
        __syncthreads();
        #pragma unroll
        for (int k = 0; k < BK; k++) {
            float a[8], b[8];
            *(float4*)(a)     = *(const float4*)&As[k][ty * 8];
            *(float4*)(a + 4) = *(const float4*)&As[k][ty * 8 + 4];
            *(float4*)(b)     = *(const float4*)&Bs[k][tx * 8];
            *(float4*)(b + 4) = *(const float4*)&Bs[k][tx * 8 + 4];
            #pragma unroll
            for (int i = 0; i < 8; i++)
                #pragma unroll
                for (int j = 0; j < 8; j++)
                    acc[i][j] += a[i] * b[j];
        }
        __syncthreads();
    }
    float* Out = useExpert ? g_eo : g_shared;
    #pragma unroll
    for (int i = 0; i < 8; i++) {
        int r = ty * 8 + i;
        if (r < nrows) {
            int orow = rowStart + r;
            float sc = useExpert ? g_permw[orow] : 1.f;
            #pragma unroll
            for (int j = 0; j < 8; j++)
                Out[(size_t)orow * LLM + colBase + tx * 8 + j] = sc * acc[i][j];
        }
    }
}

// ---------------- kernel 6: combine + LN_post -------------------------------
__global__ __launch_bounds__(256) void ln_post_kernel(
    const float* __restrict__ lng, const float* __restrict__ lnb,
    float* __restrict__ out)
{
    int t = blockIdx.x;
    int tid = threadIdx.x;
    int p0 = g_pos[2 * t + 0], p1 = g_pos[2 * t + 1];
    const float* sh = g_shared + (size_t)t * LLM;
    const float* e0 = g_eo + (size_t)p0 * LLM;
    const float* e1 = g_eo + (size_t)p1 * LLM;
    float v[8];
    float sum = 0.f, sq = 0.f;
    #pragma unroll
    for (int i = 0; i < 8; i++) {
        int j = tid + i * 256;
        float val = sh[j] + e0[j] + e1[j];
        v[i] = val; sum += val; sq += val * val;
    }
    blockReduce2(sum, sq);
    float m = sum * (1.f / LLM);
    float var = sq * (1.f / LLM) - m * m;
    float rinv = rsqrtf(var + 1e-6f);
    float* orow = out + (size_t)t * LLM;
    #pragma unroll
    for (int i = 0; i < 8; i++) {
        int j = tid + i * 256;
        orow[j] = (v[i] - m) * rinv * lng[j] + lnb[j];
    }
}

// ---------------- launcher --------------------------------------------------
extern "C" void kernel_launch(void* const* d_in, const int* in_sizes, int n_in,
                              void* d_out, int out_size)
{
    const float* x           = (const float*)d_in[0];
    const float* ln_pre_g    = (const float*)d_in[1];
    const float* ln_pre_b    = (const float*)d_in[2];
    const float* router_w    = (const float*)d_in[3];
    const float* router_b    = (const float*)d_in[4];
    const float* shared_w12  = (const float*)d_in[5];
    const float* shared_w3   = (const float*)d_in[6];
    const float* experts_w12 = (const float*)d_in[7];
    const float* experts_w3  = (const float*)d_in[8];
    const float* ln_post_g   = (const float*)d_in[9];
    const float* ln_post_b   = (const float*)d_in[10];
    float* out = (float*)d_out;

    init_kernel<<<1, 32>>>();
    ln_router_kernel<<<T_TOK, 256>>>(x, ln_pre_g, ln_pre_b, router_w, router_b);
    scan_kernel<<<1, 32>>>();
    build_kernel<<<(T_TOK + 255) / 256, 256>>>();

    const int ROWT = (T_TOK + 127) / 128;   // 94 (also covers worst-case expert)
    // shared branch
    gemm12_kernel<<<dim3(HID / 64, ROWT, 1), 256>>>(shared_w12, 0);
    gemm3_kernel <<<dim3(LLM / 128, ROWT, 1), 256>>>(shared_w3, 0);
    // expert branch (grouped GEMM over expert-sorted rows; empty tiles exit)
    gemm12_kernel<<<dim3(HID / 64, ROWT, NE), 256>>>(experts_w12, 1);
    gemm3_kernel <<<dim3(LLM / 128, ROWT, NE), 256>>>(experts_w3, 1);

    ln_post_kernel<<<T_TOK, 256>>>(ln_post_g, ln_post_b, out);
}

// round 3
// speedup vs baseline: 1.9645x; 1.9645x over previous
#include <cuda_runtime.h>
#include <math.h>
#include <stdint.h>

// ---------------- problem constants ----------------------------------------
#define T_TOK 12000          // B*S/K tokens
#define D_IN  2560           // ENC*K
#define HID   512
#define LLM   2048
#define NE    8
#define NTOP  2
#define TWO   (T_TOK*NTOP)   // 24000 (token,slot) pairs

// ---------------- static device scratch ------------------------------------
__device__ float g_nx[(size_t)T_TOK * D_IN];        // LN'd input, tf32-rounded
__device__ float g_act[(size_t)T_TOK * HID];        // shared swiglu (rounded)
__device__ float g_shared[(size_t)T_TOK * LLM];
__device__ float g_eact[(size_t)TWO * HID];         // expert swiglu (rounded)
__device__ float g_eo[(size_t)TWO * LLM];
__device__ float g_w12s[(size_t)2 * HID * D_IN];    // tf32-rounded weights
__device__ float g_w3s[(size_t)LLM * HID];
__device__ float g_w12e[(size_t)NE * 2 * HID * D_IN];
__device__ float g_w3e[(size_t)NE * LLM * HID];
__device__ int   g_idx[TWO];
__device__ float g_w[TWO];
__device__ int   g_perm[TWO];
__device__ float g_permw[TWO];
__device__ int   g_pos[TWO];
__device__ int   g_cnt[NE];
__device__ int   g_off[NE + 1];
__device__ int   g_cur[NE];

// ---------------- PTX helpers (sm_100-plain safe: sm_80-era instructions) --
__device__ __forceinline__ uint32_t smem_u32(const void* p) {
    uint32_t a;
    asm("{ .reg .u64 t; cvta.to.shared.u64 t, %1; cvt.u32.u64 %0, t; }" : "=r"(a) : "l"(p));
    return a;
}
__device__ __forceinline__ uint32_t f2tf(float f) {
    uint32_t u;
    asm("cvt.rna.tf32.f32 %0, %1;" : "=r"(u) : "f"(f));
    return u;
}
__device__ __forceinline__ float rtf(float f) { return __uint_as_float(f2tf(f)); }

__device__ __forceinline__ void cpa16(uint32_t dst, const void* src, uint32_t srcsz) {
    asm volatile("cp.async.cg.shared.global [%0], [%1], 16, %2;"
                 :: "r"(dst), "l"(src), "r"(srcsz) : "memory");
}
#define CP_COMMIT() asm volatile("cp.async.commit_group;" ::: "memory")
#define CP_WAIT1()  asm volatile("cp.async.wait_group 1;" ::: "memory")

__device__ __forceinline__ void ldsm4(uint32_t& r0, uint32_t& r1, uint32_t& r2, uint32_t& r3,
                                      uint32_t addr) {
    asm volatile("ldmatrix.sync.aligned.m8n8.x4.shared.b16 {%0,%1,%2,%3}, [%4];"
                 : "=r"(r0), "=r"(r1), "=r"(r2), "=r"(r3) : "r"(addr));
}
__device__ __forceinline__ void mma_tf32(float* c,
                                         uint32_t a0, uint32_t a1, uint32_t a2, uint32_t a3,
                                         uint32_t b0, uint32_t b1) {
    asm volatile(
        "mma.sync.aligned.m16n8k8.row.col.f32.tf32.tf32.f32 "
        "{%0,%1,%2,%3}, {%4,%5,%6,%7}, {%8,%9}, {%0,%1,%2,%3};"
        : "+f"(c[0]), "+f"(c[1]), "+f"(c[2]), "+f"(c[3])
        : "r"(a0), "r"(a1), "r"(a2), "r"(a3), "r"(b0), "r"(b1));
}

// ---------------- smem geometry ---------------------------------------------
// A/B tiles: [128 rows][36 floats] -> 144B row stride. 16B-group = (9*row + chunk) mod 8
// is a permutation over 8 rows / 8 chunks => conflict-free STS(cp.async) and ldmatrix.
#define ASTRB   144
#define STAGE_B 36864               // (128*144)*2 per stage (A then B)
#define SMEM_DYN (3 * STAGE_B)      // 110592 B

// ---------------- misc helpers ----------------------------------------------
__device__ __forceinline__ void blockReduce2(float& sum, float& sq) {
    __shared__ float ss[8], sv[8];
    #pragma unroll
    for (int o = 16; o > 0; o >>= 1) {
        sum += __shfl_down_sync(0xFFFFFFFFu, sum, o);
        sq  += __shfl_down_sync(0xFFFFFFFFu, sq,  o);
    }
    int w = threadIdx.x >> 5, l = threadIdx.x & 31;
    if (l == 0) { ss[w] = sum; sv[w] = sq; }
    __syncthreads();
    if (w == 0) {
        sum = (l < 8) ? ss[l] : 0.f;
        sq  = (l < 8) ? sv[l] : 0.f;
        #pragma unroll
        for (int o = 4; o > 0; o >>= 1) {
            sum += __shfl_down_sync(0xFFFFFFFFu, sum, o);
            sq  += __shfl_down_sync(0xFFFFFFFFu, sq,  o);
        }
        if (l == 0) { ss[0] = sum; sv[0] = sq; }
    }
    __syncthreads();
    sum = ss[0]; sq = sv[0];
}

// ---------------- kernel 0: zero counters -----------------------------------
__global__ void init_kernel() {
    int i = threadIdx.x;
    if (i < NE) { g_cnt[i] = 0; g_cur[i] = 0; }
}

// ---------------- kernel 0b: round weights to tf32 once per launch ----------
__global__ __launch_bounds__(256) void cvt_weights(
    const float4* __restrict__ s12, const float4* __restrict__ s3,
    const float4* __restrict__ e12, const float4* __restrict__ e3)
{
    const int N1 = 2 * HID * D_IN / 4;
    const int N2 = LLM * HID / 4;
    const int N3 = NE * 2 * HID * D_IN / 4;
    const int N4 = NE * LLM * HID / 4;
    const int total = N1 + N2 + N3 + N4;
    for (int i = blockIdx.x * blockDim.x + threadIdx.x; i < total;
         i += gridDim.x * blockDim.x) {
        float4 v; float4* dst;
        int j = i;
        if (j < N1)            { v = s12[j]; dst = (float4*)g_w12s + j; }
        else if ((j -= N1) < N2) { v = s3[j];  dst = (float4*)g_w3s  + j; }
        else if ((j -= N2) < N3) { v = e12[j]; dst = (float4*)g_w12e + j; }
        else { j -= N3;          v = e3[j];  dst = (float4*)g_w3e  + j; }
        v.x = rtf(v.x); v.y = rtf(v.y); v.z = rtf(v.z); v.w = rtf(v.w);
        *dst = v;
    }
}

// ---------------- kernel 1: LN_pre + router/top2 -----------------------------
__global__ __launch_bounds__(256) void ln_router_kernel(
    const float* __restrict__ x,
    const float* __restrict__ lng, const float* __restrict__ lnb,
    const float* __restrict__ rw,  const float* __restrict__ rb)
{
    int t = blockIdx.x;
    const float* xr = x + (size_t)t * D_IN;
    __shared__ float s_nx[D_IN];
    __shared__ float s_logit[NE];
    int tid = threadIdx.x;

    float v[10];
    float sum = 0.f, sq = 0.f;
    #pragma unroll
    for (int i = 0; i < 10; i++) {
        v[i] = xr[tid + i * 256];
        sum += v[i]; sq += v[i] * v[i];
    }
    blockReduce2(sum, sq);
    float m = sum * (1.f / D_IN);
    float var = sq * (1.f / D_IN) - m * m;
    float rinv = rsqrtf(var + 1e-6f);
    float* nxr = g_nx + (size_t)t * D_IN;
    #pragma unroll
    for (int i = 0; i < 10; i++) {
        int j = tid + i * 256;
        float nv = (v[i] - m) * rinv * lng[j] + lnb[j];
        s_nx[j] = nv;            // full precision for router
        nxr[j] = rtf(nv);        // tf32-rounded for GEMM A operand
    }
    __syncthreads();

    int w = tid >> 5, lane = tid & 31;
    float acc = 0.f;
    const float* rwr = rw + (size_t)w * D_IN;
    for (int i = lane; i < D_IN; i += 32) acc += s_nx[i] * rwr[i];
    #pragma unroll
    for (int o = 16; o > 0; o >>= 1) acc += __shfl_down_sync(0xFFFFFFFFu, acc, o);
    if (lane == 0) s_logit[w] = acc + rb[w];
    __syncthreads();

    if (tid == 0) {
        float mx = s_logit[0];
        #pragma unroll
        for (int e = 1; e < NE; e++) mx = fmaxf(mx, s_logit[e]);
        float p[NE], se = 0.f;
        #pragma unroll
        for (int e = 0; e < NE; e++) { p[e] = __expf(s_logit[e] - mx); se += p[e]; }
        float rse = 1.f / se;
        #pragma unroll
        for (int e = 0; e < NE; e++) p[e] *= rse;
        int i0 = 0;
        #pragma unroll
        for (int e = 1; e < NE; e++) if (p[e] > p[i0]) i0 = e;
        int i1 = (i0 == 0) ? 1 : 0;
        #pragma unroll
        for (int e = 0; e < NE; e++) if (e != i0 && p[e] > p[i1]) i1 = e;
        float s2 = p[i0] + p[i1] + 1e-20f;
        g_idx[2 * t + 0] = i0; g_w[2 * t + 0] = p[i0] / s2;
        g_idx[2 * t + 1] = i1; g_w[2 * t + 1] = p[i1] / s2;
        atomicAdd(&g_cnt[i0], 1);
        atomicAdd(&g_cnt[i1], 1);
    }
}

// ---------------- kernel 2/3: scan + permutation ----------------------------
__global__ void scan_kernel() {
    if (threadIdx.x == 0) {
        int o = 0;
        for (int e = 0; e < NE; e++) { g_off[e] = o; o += g_cnt[e]; }
        g_off[NE] = o;
    }
}
__global__ void build_kernel() {
    int t = blockIdx.x * blockDim.x + threadIdx.x;
    if (t >= T_TOK) return;
    #pragma unroll
    for (int k = 0; k < NTOP; k++) {
        int e = g_idx[2 * t + k];
        int p = g_off[e] + atomicAdd(&g_cur[e], 1);
        g_perm[p]  = t;
        g_permw[p] = g_w[2 * t + k];
        g_pos[2 * t + k] = p;
    }
}

// ============================================================================
// kernel 4: mma.sync tf32 GEMM w12 + fused SwiGLU
//   CTA 128x128 (64 act cols: gate rows 0-63, val rows 64-127), K=2560
// ============================================================================
__global__ __launch_bounds__(128) void gemm12_mma(int useGather)
{
    int rowStart, nrows;
    const float* W;
    if (useGather) {
        int e = blockIdx.z;
        int re = g_off[e + 1];
        rowStart = g_off[e] + blockIdx.y * 128;
        if (rowStart >= re) return;
        nrows = min(128, re - rowStart);
        W = g_w12e + (size_t)e * (2 * HID) * D_IN;
    } else {
        rowStart = blockIdx.y * 128;
        nrows = min(128, T_TOK - rowStart);
        W = g_w12s;
    }
    const int colBase = blockIdx.x * 64;

    extern __shared__ __align__(16) float smem[];
    __shared__ int s_perm[128];
    const uint32_t sbase = smem_u32(smem);
    const int tid = threadIdx.x, lane = tid & 31, wid = tid >> 5;

    if (tid < 128)
        s_perm[tid] = (useGather && tid < nrows) ? g_perm[rowStart + tid] : 0;
    __syncthreads();

    // per-thread global row pointers (thread t owns tile row t)
    const int rvalid = (tid < nrows) ? 16 : 0;
    const float* srcA = useGather
        ? g_nx + (size_t)s_perm[tid] * D_IN
        : g_nx + (size_t)(rowStart + min(tid, nrows - 1)) * D_IN;
    const int wrow = (tid < 64) ? (colBase + tid) : (HID + colBase + (tid - 64));
    const float* srcB = W + (size_t)wrow * D_IN;

    auto fill = [&](int s, int k0) {
        uint32_t a = sbase + s * STAGE_B + tid * ASTRB;
        uint32_t b = a + 128 * ASTRB;
        #pragma unroll
        for (int j = 0; j < 8; j++) {
            cpa16(a + j * 16, srcA + k0 + j * 4, rvalid);
            cpa16(b + j * 16, srcB + k0 + j * 4, 16);
        }
        CP_COMMIT();
    };

    fill(0, 0);
    fill(1, 32);

    float acc[4][8][4] = {};
    const int wm = (wid >> 1) * 64, wn = (wid & 1) * 64;
    const int sub = lane >> 3, l7 = lane & 7;
    const int a_row = (sub & 1) * 8 + l7, a_col = (sub >> 1) * 4;
    const int b_row = ((sub >> 1) & 1) * 8 + l7, b_col = (sub & 1) * 4;

    const int NK = D_IN / 32;   // 80
    for (int kt = 0; kt < NK; kt++) {
        CP_WAIT1();
        __syncthreads();
        if (kt + 2 < NK) fill((kt + 2) % 3, (kt + 2) * 32);

        uint32_t abase = sbase + (kt % 3) * STAGE_B;
        uint32_t bbase = abase + 128 * ASTRB;
        #pragma unroll
        for (int k8 = 0; k8 < 4; k8++) {
            uint32_t a[4][4], b[4][4];
            #pragma unroll
            for (int mf = 0; mf < 4; mf++)
                ldsm4(a[mf][0], a[mf][1], a[mf][2], a[mf][3],
                      abase + (wm + mf * 16 + a_row) * ASTRB + (k8 * 8 + a_col) * 4);
            #pragma unroll
            for (int j = 0; j < 4; j++)
                ldsm4(b[j][0], b[j][1], b[j][2], b[j][3],
                      bbase + (wn + j * 16 + b_row) * ASTRB + (k8 * 8 + b_col) * 4);
            #pragma unroll
            for (int mf = 0; mf < 4; mf++)
                #pragma unroll
                for (int j = 0; j < 4; j++) {
                    mma_tf32(acc[mf][2 * j],     a[mf][0], a[mf][1], a[mf][2], a[mf][3], b[j][0], b[j][1]);
                    mma_tf32(acc[mf][2 * j + 1], a[mf][0], a[mf][1], a[mf][2], a[mf][3], b[j][2], b[j][3]);
                }
        }
    }
    __syncthreads();

    // epilogue: C -> smem stage, SwiGLU, coalesced global store
    float* st = smem;   // [128][132]
    const int cg = lane >> 2, ct = lane & 3;
    #pragma unroll
    for (int mf = 0; mf < 4; mf++) {
        int row = wm + mf * 16 + cg;
        #pragma unroll
        for (int nf = 0; nf < 8; nf++) {
            int col = wn + nf * 8 + ct * 2;
            *(float2*)(st + row * 132 + col)       = make_float2(acc[mf][nf][0], acc[mf][nf][1]);
            *(float2*)(st + (row + 8) * 132 + col) = make_float2(acc[mf][nf][2], acc[mf][nf][3]);
        }
    }
    __syncthreads();

    float* Out = useGather ? g_eact : g_act;
    #pragma unroll
    for (int i = 0; i < 16; i++) {
        int f = tid + i * 128;
        int r = f >> 4, c4 = f & 15;
        if (r < nrows) {
            float4 gg = *(float4*)(st + r * 132 + c4 * 4);
            float4 vv = *(float4*)(st + r * 132 + 64 + c4 * 4);
            float4 o;
            o.x = rtf(gg.x / (1.f + __expf(-gg.x)) * vv.x);
            o.y = rtf(gg.y / (1.f + __expf(-gg.y)) * vv.y);
            o.z = rtf(gg.z / (1.f + __expf(-gg.z)) * vv.z);
            o.w = rtf(gg.w / (1.f + __expf(-gg.w)) * vv.w);
            *(float4*)(Out + (size_t)(rowStart + r) * HID + colBase + c4 * 4) = o;
        }
    }
}

// ============================================================================
// kernel 5: mma.sync tf32 GEMM w3 (+ fused routing weight), K = 512
// ============================================================================
__global__ __launch_bounds__(128) void gemm3_mma(int useExpert)
{
    int rowStart, nrows;
    const float* W;
    if (useExpert) {
        int e = blockIdx.z;
        int re = g_off[e + 1];
        rowStart = g_off[e] + blockIdx.y * 128;
        if (rowStart >= re) return;
        nrows = min(128, re - rowStart);
        W = g_w3e + (size_t)e * LLM * HID;
    } else {
        rowStart = blockIdx.y * 128;
        nrows = min(128, T_TOK - rowStart);
        W = g_w3s;
    }
    const int colBase = blockIdx.x * 128;
    const float* Act = useExpert ? g_eact : g_act;

    extern __shared__ __align__(16) float smem[];
    const uint32_t sbase = smem_u32(smem);
    const int tid = threadIdx.x, lane = tid & 31, wid = tid >> 5;

    const int rvalid = (tid < nrows) ? 16 : 0;
    const float* srcA = Act + (size_t)(rowStart + min(tid, nrows - 1)) * HID;
    const float* srcB = W + (size_t)(colBase + tid) * HID;

    auto fill = [&](int s, int k0) {
        uint32_t a = sbase + s * STAGE_B + tid * ASTRB;
        uint32_t b = a + 128 * ASTRB;
        #pragma unroll
        for (int j = 0; j < 8; j++) {
            cpa16(a + j * 16, srcA + k0 + j * 4, rvalid);
            cpa16(b + j * 16, srcB + k0 + j * 4, 16);
        }
        CP_COMMIT();
    };

    fill(0, 0);
    fill(1, 32);

    float acc[4][8][4] = {};
    const int wm = (wid >> 1) * 64, wn = (wid & 1) * 64;
    const int sub = lane >> 3, l7 = lane & 7;
    const int a_row = (sub & 1) * 8 + l7, a_col = (sub >> 1) * 4;
    const int b_row = ((sub >> 1) & 1) * 8 + l7, b_col = (sub & 1) * 4;

    const int NK = HID / 32;    // 16
    for (int kt = 0; kt < NK; kt++) {
        CP_WAIT1();
        __syncthreads();
        if (kt + 2 < NK) fill((kt + 2) % 3, (kt + 2) * 32);

        uint32_t abase = sbase + (kt % 3) * STAGE_B;
        uint32_t bbase = abase + 128 * ASTRB;
        #pragma unroll
        for (int k8 = 0; k8 < 4; k8++) {
            uint32_t a[4][4], b[4][4];
            #pragma unroll
            for (int mf = 0; mf < 4; mf++)
                ldsm4(a[mf][0], a[mf][1], a[mf][2], a[mf][3],
                      abase + (wm + mf * 16 + a_row) * ASTRB + (k8 * 8 + a_col) * 4);
            #pragma unroll
            for (int j = 0; j < 4; j++)
                ldsm4(b[j][0], b[j][1], b[j][2], b[j][3],
                      bbase + (wn + j * 16 + b_row) * ASTRB + (k8 * 8 + b_col) * 4);
            #pragma unroll
            for (int mf = 0; mf < 4; mf++)
                #pragma unroll
                for (int j = 0; j < 4; j++) {
                    mma_tf32(acc[mf][2 * j],     a[mf][0], a[mf][1], a[mf][2], a[mf][3], b[j][0], b[j][1]);
                    mma_tf32(acc[mf][2 * j + 1], a[mf][0], a[mf][1], a[mf][2], a[mf][3], b[j][2], b[j][3]);
                }
        }
    }
    __syncthreads();

    float* st = smem;   // [128][132]
    const int cg = lane >> 2, ct = lane & 3;
    #pragma unroll
    for (int mf = 0; mf < 4; mf++) {
        int row = wm + mf * 16 + cg;
        #pragma unroll
        for (int nf = 0; nf < 8; nf++) {
            int col = wn + nf * 8 + ct * 2;
            *(float2*)(st + row * 132 + col)       = make_float2(acc[mf][nf][0], acc[mf][nf][1]);
            *(float2*)(st + (row + 8) * 132 + col) = make_float2(acc[mf][nf][2], acc[mf][nf][3]);
        }
    }
    __syncthreads();

    float* Out = useExpert ? g_eo : g_shared;
    #pragma unroll
    for (int i = 0; i < 32; i++) {
        int f = tid + i * 128;
        int r = f >> 5, c4 = f & 31;
        if (r < nrows) {
            float sc = useExpert ? g_permw[rowStart + r] : 1.f;
            float4 v = *(float4*)(st + r * 132 + c4 * 4);
            v.x *= sc; v.y *= sc; v.z *= sc; v.w *= sc;
            *(float4*)(Out + (size_t)(rowStart + r) * LLM + colBase + c4 * 4) = v;
        }
    }
}

// ---------------- kernel 6: combine + LN_post --------------------------------
__global__ __launch_bounds__(256) void ln_post_kernel(
    const float* __restrict__ lng, const float* __restrict__ lnb,
    float* __restrict__ out)
{
    int t = blockIdx.x;
    int tid = threadIdx.x;
    int p0 = g_pos[2 * t + 0], p1 = g_pos[2 * t + 1];
    const float* sh = g_shared + (size_t)t * LLM;
    const float* e0 = g_eo + (size_t)p0 * LLM;
    const float* e1 = g_eo + (size_t)p1 * LLM;
    float v[8];
    float sum = 0.f, sq = 0.f;
    #pragma unroll
    for (int i = 0; i < 8; i++) {
        int j = tid + i * 256;
        float val = sh[j] + e0[j] + e1[j];
        v[i] = val; sum += val; sq += val * val;
    }
    blockReduce2(sum, sq);
    float m = sum * (1.f / LLM);
    float var = sq * (1.f / LLM) - m * m;
    float rinv = rsqrtf(var + 1e-6f);
    float* orow = out + (size_t)t * LLM;
    #pragma unroll
    for (int i = 0; i < 8; i++) {
        int j = tid + i * 256;
        orow[j] = (v[i] - m) * rinv * lng[j] + lnb[j];
    }
}

// ---------------- launcher ----------------------------------------------------
extern "C" void kernel_launch(void* const* d_in, const int* in_sizes, int n_in,
                              void* d_out, int out_size)
{
    const float* x           = (const float*)d_in[0];
    const float* ln_pre_g    = (const float*)d_in[1];
    const float* ln_pre_b    = (const float*)d_in[2];
    const float* router_w    = (const float*)d_in[3];
    const float* router_b    = (const float*)d_in[4];
    const float* shared_w12  = (const float*)d_in[5];
    const float* shared_w3   = (const float*)d_in[6];
    const float* experts_w12 = (const float*)d_in[7];
    const float* experts_w3  = (const float*)d_in[8];
    const float* ln_post_g   = (const float*)d_in[9];
    const float* ln_post_b   = (const float*)d_in[10];
    float* out = (float*)d_out;

    cudaFuncSetAttribute(gemm12_mma, cudaFuncAttributeMaxDynamicSharedMemorySize, SMEM_DYN);
    cudaFuncSetAttribute(gemm3_mma,  cudaFuncAttributeMaxDynamicSharedMemorySize, SMEM_DYN);

    init_kernel<<<1, 32>>>();
    cvt_weights<<<4096, 256>>>((const float4*)shared_w12, (const float4*)shared_w3,
                               (const float4*)experts_w12, (const float4*)experts_w3);
    ln_router_kernel<<<T_TOK, 256>>>(x, ln_pre_g, ln_pre_b, router_w, router_b);
    scan_kernel<<<1, 32>>>();
    build_kernel<<<(T_TOK + 255) / 256, 256>>>();

    const int MT = (T_TOK + 127) / 128;   // 94 M-tiles (covers worst-case expert too)

    // shared branch
    gemm12_mma<<<dim3(HID / 64, MT, 1), 128, SMEM_DYN>>>(0);
    gemm3_mma <<<dim3(LLM / 128, MT, 1), 128, SMEM_DYN>>>(0);
    // expert branch (grouped over expert-sorted rows; empty tiles exit early)
    gemm12_mma<<<dim3(HID / 64, MT, NE), 128, SMEM_DYN>>>(1);
    gemm3_mma <<<dim3(LLM / 128, MT, NE), 128, SMEM_DYN>>>(1);

    ln_post_kernel<<<T_TOK, 256>>>(ln_post_g, ln_post_b, out);
}

// round 5
// speedup vs baseline: 3.4698x; 1.7662x over previous
#include <cuda_runtime.h>
#include <cuda_fp16.h>
#include <math.h>
#include <stdint.h>

// ---------------- problem constants ----------------------------------------
#define T_TOK 12000          // B*S/K tokens
#define D_IN  2560           // ENC*K
#define HID   512
#define LLM   2048
#define NE    8
#define NTOP  2
#define TWO   (T_TOK*NTOP)   // 24000 (token,slot) pairs

// ---------------- static device scratch ------------------------------------
__device__ __half g_nx[(size_t)T_TOK * D_IN];       // LN'd input (fp16)
__device__ __half g_act[(size_t)T_TOK * HID];       // shared swiglu (fp16)
__device__ float  g_shared[(size_t)T_TOK * LLM];
__device__ __half g_eact[(size_t)TWO * HID];        // expert swiglu (fp16)
__device__ float  g_eo[(size_t)TWO * LLM];
__device__ __half g_w12s[(size_t)2 * HID * D_IN];   // fp16 weights
__device__ __half g_w3s[(size_t)LLM * HID];
__device__ __half g_w12e[(size_t)NE * 2 * HID * D_IN];
__device__ __half g_w3e[(size_t)NE * LLM * HID];
__device__ int   g_idx[TWO];
__device__ float g_w[TWO];
__device__ int   g_perm[TWO];
__device__ float g_permw[TWO];
__device__ int   g_pos[TWO];
__device__ int   g_cnt[NE];
__device__ int   g_off[NE + 1];
__device__ int   g_cur[NE];

// ---------------- PTX helpers (sm_80-era; safe for plain sm_100) -----------
__device__ __forceinline__ uint32_t smem_u32(const void* p) {
    uint32_t a;
    asm("{ .reg .u64 t; cvta.to.shared.u64 t, %1; cvt.u32.u64 %0, t; }" : "=r"(a) : "l"(p));
    return a;
}
__device__ __forceinline__ void cpa16(uint32_t dst, const void* src, uint32_t srcsz) {
    asm volatile("cp.async.cg.shared.global [%0], [%1], 16, %2;"
                 :: "r"(dst), "l"(src), "r"(srcsz) : "memory");
}
#define CP_COMMIT() asm volatile("cp.async.commit_group;" ::: "memory")
#define CP_WAIT1()  asm volatile("cp.async.wait_group 1;" ::: "memory")

__device__ __forceinline__ void ldsm4(uint32_t& r0, uint32_t& r1, uint32_t& r2, uint32_t& r3,
                                      uint32_t addr) {
    asm volatile("ldmatrix.sync.aligned.m8n8.x4.shared.b16 {%0,%1,%2,%3}, [%4];"
                 : "=r"(r0), "=r"(r1), "=r"(r2), "=r"(r3) : "r"(addr));
}
__device__ __forceinline__ void mma_f16(float* c,
                                        uint32_t a0, uint32_t a1, uint32_t a2, uint32_t a3,
                                        uint32_t b0, uint32_t b1) {
    asm volatile(
        "mma.sync.aligned.m16n8k16.row.col.f32.f16.f16.f32 "
        "{%0,%1,%2,%3}, {%4,%5,%6,%7}, {%8,%9}, {%0,%1,%2,%3};"
        : "+f"(c[0]), "+f"(c[1]), "+f"(c[2]), "+f"(c[3])
        : "r"(a0), "r"(a1), "r"(a2), "r"(a3), "r"(b0), "r"(b1));
}

// ---------------- smem geometry ---------------------------------------------
// Tiles: [128 rows][64 halfs + pad] -> 144B row stride. 16B-group index =
// (9*row + chunk) mod 8 => conflict-free cp.async stores and ldmatrix reads.
#define ASTRB   144
#define STAGE_B 36864               // (128*144) * 2 (A then B) per stage
#define SMEM_DYN (3 * STAGE_B)      // 110592 B, 3-stage pipeline

// ---------------- misc helpers ----------------------------------------------
__device__ __forceinline__ void blockReduce2(float& sum, float& sq) {
    __shared__ float ss[8], sv[8];
    #pragma unroll
    for (int o = 16; o > 0; o >>= 1) {
        sum += __shfl_down_sync(0xFFFFFFFFu, sum, o);
        sq  += __shfl_down_sync(0xFFFFFFFFu, sq,  o);
    }
    int w = threadIdx.x >> 5, l = threadIdx.x & 31;
    if (l == 0) { ss[w] = sum; sv[w] = sq; }
    __syncthreads();
    if (w == 0) {
        sum = (l < 8) ? ss[l] : 0.f;
        sq  = (l < 8) ? sv[l] : 0.f;
        #pragma unroll
        for (int o = 4; o > 0; o >>= 1) {
            sum += __shfl_down_sync(0xFFFFFFFFu, sum, o);
            sq  += __shfl_down_sync(0xFFFFFFFFu, sq,  o);
        }
        if (l == 0) { ss[0] = sum; sv[0] = sq; }
    }
    __syncthreads();
    sum = ss[0]; sq = sv[0];
}

// ---------------- kernel 0: zero counters -----------------------------------
__global__ void init_kernel() {
    int i = threadIdx.x;
    if (i < NE) { g_cnt[i] = 0; g_cur[i] = 0; }
}

// ---------------- kernel 0b: convert weights to fp16 once per launch --------
__global__ __launch_bounds__(256) void cvt_weights(
    const float4* __restrict__ s12, const float4* __restrict__ s3,
    const float4* __restrict__ e12, const float4* __restrict__ e3)
{
    const int N1 = 2 * HID * D_IN / 4;
    const int N2 = LLM * HID / 4;
    const int N3 = NE * 2 * HID * D_IN / 4;
    const int N4 = NE * LLM * HID / 4;
    const int total = N1 + N2 + N3 + N4;
    for (int i = blockIdx.x * blockDim.x + threadIdx.x; i < total;
         i += gridDim.x * blockDim.x) {
        float4 v; __half2* dst;
        int j = i;
        if (j < N1)              { v = s12[j]; dst = (__half2*)g_w12s + 2 * j; }
        else if ((j -= N1) < N2) { v = s3[j];  dst = (__half2*)g_w3s  + 2 * j; }
        else if ((j -= N2) < N3) { v = e12[j]; dst = (__half2*)g_w12e + 2 * j; }
        else { j -= N3;           v = e3[j];  dst = (__half2*)g_w3e  + 2 * j; }
        dst[0] = __floats2half2_rn(v.x, v.y);
        dst[1] = __floats2half2_rn(v.z, v.w);
    }
}

// ---------------- kernel 1: LN_pre + router/top2 -----------------------------
__global__ __launch_bounds__(256) void ln_router_kernel(
    const float* __restrict__ x,
    const float* __restrict__ lng, const float* __restrict__ lnb,
    const float* __restrict__ rw,  const float* __restrict__ rb)
{
    int t = blockIdx.x;
    const float* xr = x + (size_t)t * D_IN;
    __shared__ float s_nx[D_IN];
    __shared__ float s_logit[NE];
    int tid = threadIdx.x;

    float v[10];
    float sum = 0.f, sq = 0.f;
    #pragma unroll
    for (int i = 0; i < 10; i++) {
        v[i] = xr[tid + i * 256];
        sum += v[i]; sq += v[i] * v[i];
    }
    blockReduce2(sum, sq);
    float m = sum * (1.f / D_IN);
    float var = sq * (1.f / D_IN) - m * m;
    float rinv = rsqrtf(var + 1e-6f);
    __half* nxr = g_nx + (size_t)t * D_IN;
    #pragma unroll
    for (int i = 0; i < 10; i++) {
        int j = tid + i * 256;
        float nv = (v[i] - m) * rinv * lng[j] + lnb[j];
        s_nx[j] = nv;                         // full precision for router
        nxr[j] = __float2half_rn(nv);         // fp16 GEMM A operand
    }
    __syncthreads();

    int w = tid >> 5, lane = tid & 31;
    float acc = 0.f;
    const float* rwr = rw + (size_t)w * D_IN;
    for (int i = lane; i < D_IN; i += 32) acc += s_nx[i] * rwr[i];
    #pragma unroll
    for (int o = 16; o > 0; o >>= 1) acc += __shfl_down_sync(0xFFFFFFFFu, acc, o);
    if (lane == 0) s_logit[w] = acc + rb[w];
    __syncthreads();

    if (tid == 0) {
        float mx = s_logit[0];
        #pragma unroll
        for (int e = 1; e < NE; e++) mx = fmaxf(mx, s_logit[e]);
        float p[NE], se = 0.f;
        #pragma unroll
        for (int e = 0; e < NE; e++) { p[e] = __expf(s_logit[e] - mx); se += p[e]; }
        float rse = 1.f / se;
        #pragma unroll
        for (int e = 0; e < NE; e++) p[e] *= rse;
        int i0 = 0;
        #pragma unroll
        for (int e = 1; e < NE; e++) if (p[e] > p[i0]) i0 = e;
        int i1 = (i0 == 0) ? 1 : 0;
        #pragma unroll
        for (int e = 0; e < NE; e++) if (e != i0 && p[e] > p[i1]) i1 = e;
        float s2 = p[i0] + p[i1] + 1e-20f;
        g_idx[2 * t + 0] = i0; g_w[2 * t + 0] = p[i0] / s2;
        g_idx[2 * t + 1] = i1; g_w[2 * t + 1] = p[i1] / s2;
        atomicAdd(&g_cnt[i0], 1);
        atomicAdd(&g_cnt[i1], 1);
    }
}

// ---------------- kernel 2/3: scan + permutation ----------------------------
__global__ void scan_kernel() {
    if (threadIdx.x == 0) {
        int o = 0;
        for (int e = 0; e < NE; e++) { g_off[e] = o; o += g_cnt[e]; }
        g_off[NE] = o;
    }
}
__global__ void build_kernel() {
    int t = blockIdx.x * blockDim.x + threadIdx.x;
    if (t >= T_TOK) return;
    #pragma unroll
    for (int k = 0; k < NTOP; k++) {
        int e = g_idx[2 * t + k];
        int p = g_off[e] + atomicAdd(&g_cur[e], 1);
        g_perm[p]  = t;
        g_permw[p] = g_w[2 * t + k];
        g_pos[2 * t + k] = p;
    }
}

// ============================================================================
// fp16 mma.sync GEMM core: CTA 128x128, BK=64, 4 warps (warp tile 64x64)
// ============================================================================
#define GEMM_FRAGS                                                            \
    const int lane = threadIdx.x & 31, wid = threadIdx.x >> 5;                \
    const int wm = (wid >> 1) * 64, wn = (wid & 1) * 64;                      \
    const int l16 = lane & 15, lh = lane >> 4;                                \
    const int bg = lane >> 3;                                                 \
    const int b_row = ((bg & 1) << 3) + (lane & 7), b_ch = bg >> 1;

#define GEMM_KSTEP(abase, bbase)                                              \
    _Pragma("unroll")                                                         \
    for (int step = 0; step < 4; step++) {                                    \
        uint32_t a[4][4], b[4][4];                                            \
        _Pragma("unroll")                                                     \
        for (int mf = 0; mf < 4; mf++)                                        \
            ldsm4(a[mf][0], a[mf][1], a[mf][2], a[mf][3],                     \
                  (abase) + (wm + mf * 16 + l16) * ASTRB + (step * 2 + lh) * 16); \
        _Pragma("unroll")                                                     \
        for (int nb = 0; nb < 4; nb++)                                        \
            ldsm4(b[nb][0], b[nb][1], b[nb][2], b[nb][3],                     \
                  (bbase) + (wn + nb * 16 + b_row) * ASTRB + (step * 2 + b_ch) * 16); \
        _Pragma("unroll")                                                     \
        for (int mf = 0; mf < 4; mf++)                                        \
            _Pragma("unroll")                                                 \
            for (int nb = 0; nb < 4; nb++) {                                  \
                mma_f16(acc[mf][2 * nb],     a[mf][0], a[mf][1], a[mf][2], a[mf][3], b[nb][0], b[nb][2]); \
                mma_f16(acc[mf][2 * nb + 1], a[mf][0], a[mf][1], a[mf][2], a[mf][3], b[nb][1], b[nb][3]); \
            }                                                                 \
    }

#define GEMM_EPI_STAGE(st)                                                    \
    {                                                                         \
        const int cg = lane >> 2, ct = lane & 3;                              \
        _Pragma("unroll")                                                     \
        for (int mf = 0; mf < 4; mf++) {                                      \
            int row = wm + mf * 16 + cg;                                      \
            _Pragma("unroll")                                                 \
            for (int nf = 0; nf < 8; nf++) {                                  \
                int col = wn + nf * 8 + ct * 2;                               \
                *(float2*)((st) + row * 132 + col)       = make_float2(acc[mf][nf][0], acc[mf][nf][1]); \
                *(float2*)((st) + (row + 8) * 132 + col) = make_float2(acc[mf][nf][2], acc[mf][nf][3]); \
            }                                                                 \
        }                                                                     \
    }

// ============================================================================
// kernel 4: GEMM w12 + fused SwiGLU (output fp16 activations)
// ============================================================================
__global__ __launch_bounds__(128) void gemm12_mma(int useGather)
{
    int rowStart, nrows;
    const __half* W;
    if (useGather) {
        int e = blockIdx.z;
        int re = g_off[e + 1];
        rowStart = g_off[e] + blockIdx.y * 128;
        if (rowStart >= re) return;
        nrows = min(128, re - rowStart);
        W = g_w12e + (size_t)e * (2 * HID) * D_IN;
    } else {
        rowStart = blockIdx.y * 128;
        nrows = min(128, T_TOK - rowStart);
        W = g_w12s;
    }
    const int colBase = blockIdx.x * 64;

    extern __shared__ __align__(16) float smem[];
    __shared__ int s_perm[128];
    const uint32_t sbase = smem_u32(smem);
    const int tid = threadIdx.x;

    if (tid < 128)
        s_perm[tid] = (useGather && tid < nrows) ? g_perm[rowStart + tid] : 0;
    __syncthreads();

    const int rvalid = (tid < nrows) ? 16 : 0;
    const __half* srcA = useGather
        ? g_nx + (size_t)s_perm[tid] * D_IN
        : g_nx + (size_t)(rowStart + min(tid, nrows - 1)) * D_IN;
    const int wrow = (tid < 64) ? (colBase + tid) : (HID + colBase + (tid - 64));
    const __half* srcB = W + (size_t)wrow * D_IN;

    auto fill = [&](int s, int k0) {
        uint32_t a = sbase + s * STAGE_B + tid * ASTRB;
        uint32_t b = a + 128 * ASTRB;
        #pragma unroll
        for (int j = 0; j < 8; j++) {
            cpa16(a + j * 16, srcA + k0 + j * 8, rvalid);
            cpa16(b + j * 16, srcB + k0 + j * 8, 16);
        }
        CP_COMMIT();
    };

    fill(0, 0);
    fill(1, 64);

    float acc[4][8][4] = {};
    GEMM_FRAGS

    const int NK = D_IN / 64;   // 40
    for (int kt = 0; kt < NK; kt++) {
        CP_WAIT1();
        __syncthreads();
        if (kt + 2 < NK) fill((kt + 2) % 3, (kt + 2) * 64);
        uint32_t abase = sbase + (kt % 3) * STAGE_B;
        uint32_t bbase = abase + 128 * ASTRB;
        GEMM_KSTEP(abase, bbase)
    }
    __syncthreads();

    float* st = smem;   // [128][132]
    GEMM_EPI_STAGE(st)
    __syncthreads();

    __half* Out = useGather ? g_eact : g_act;
    #pragma unroll
    for (int i = 0; i < 16; i++) {
        int f = tid + i * 128;
        int r = f >> 4, c4 = f & 15;
        if (r < nrows) {
            float4 gg = *(float4*)(st + r * 132 + c4 * 4);
            float4 vv = *(float4*)(st + r * 132 + 64 + c4 * 4);
            __half2 h0 = __floats2half2_rn(gg.x / (1.f + __expf(-gg.x)) * vv.x,
                                           gg.y / (1.f + __expf(-gg.y)) * vv.y);
            __half2 h1 = __floats2half2_rn(gg.z / (1.f + __expf(-gg.z)) * vv.z,
                                           gg.w / (1.f + __expf(-gg.w)) * vv.w);
            uint32_t u0, u1;
            u0 = *(uint32_t*)&h0;
            u1 = *(uint32_t*)&h1;
            *(uint2*)(Out + (size_t)(rowStart + r) * HID + colBase + c4 * 4) =
                make_uint2(u0, u1);
        }
    }
}

// ============================================================================
// kernel 5: GEMM w3 (+ fused routing weight), K = 512, fp32 output
// ============================================================================
__global__ __launch_bounds__(128) void gemm3_mma(int useExpert)
{
    int rowStart, nrows;
    const __half* W;
    if (useExpert) {
        int e = blockIdx.z;
        int re = g_off[e + 1];
        rowStart = g_off[e] + blockIdx.y * 128;
        if (rowStart >= re) return;
        nrows = min(128, re - rowStart);
        W = g_w3e + (size_t)e * LLM * HID;
    } else {
        rowStart = blockIdx.y * 128;
        nrows = min(128, T_TOK - rowStart);
        W = g_w3s;
    }
    const int colBase = blockIdx.x * 128;
    const __half* Act = useExpert ? g_eact : g_act;

    extern __shared__ __align__(16) float smem[];
    const uint32_t sbase = smem_u32(smem);
    const int tid = threadIdx.x;

    const int rvalid = (tid < nrows) ? 16 : 0;
    const __half* srcA = Act + (size_t)(rowStart + min(tid, nrows - 1)) * HID;
    const __half* srcB = W + (size_t)(colBase + tid) * HID;

    auto fill = [&](int s, int k0) {
        uint32_t a = sbase + s * STAGE_B + tid * ASTRB;
        uint32_t b = a + 128 * ASTRB;
        #pragma unroll
        for (int j = 0; j < 8; j++) {
            cpa16(a + j * 16, srcA + k0 + j * 8, rvalid);
            cpa16(b + j * 16, srcB + k0 + j * 8, 16);
        }
        CP_COMMIT();
    };

    fill(0, 0);
    fill(1, 64);

    float acc[4][8][4] = {};
    GEMM_FRAGS

    const int NK = HID / 64;    // 8
    for (int kt = 0; kt < NK; kt++) {
        CP_WAIT1();
        __syncthreads();
        if (kt + 2 < NK) fill((kt + 2) % 3, (kt + 2) * 64);
        uint32_t abase = sbase + (kt % 3) * STAGE_B;
        uint32_t bbase = abase + 128 * ASTRB;
        GEMM_KSTEP(abase, bbase)
    }
    __syncthreads();

    float* st = smem;   // [128][132]
    GEMM_EPI_STAGE(st)
    __syncthreads();

    float* Out = useExpert ? g_eo : g_shared;
    #pragma unroll
    for (int i = 0; i < 32; i++) {
        int f = tid + i * 128;
        int r = f >> 5, c4 = f & 31;
        if (r < nrows) {
            float sc = useExpert ? g_permw[rowStart + r] : 1.f;
            float4 v = *(float4*)(st + r * 132 + c4 * 4);
            v.x *= sc; v.y *= sc; v.z *= sc; v.w *= sc;
            *(float4*)(Out + (size_t)(rowStart + r) * LLM + colBase + c4 * 4) = v;
        }
    }
}

// ---------------- kernel 6: combine + LN_post --------------------------------
__global__ __launch_bounds__(256) void ln_post_kernel(
    const float* __restrict__ lng, const float* __restrict__ lnb,
    float* __restrict__ out)
{
    int t = blockIdx.x;
    int tid = threadIdx.x;
    int p0 = g_pos[2 * t + 0], p1 = g_pos[2 * t + 1];
    const float* sh = g_shared + (size_t)t * LLM;
    const float* e0 = g_eo + (size_t)p0 * LLM;
    const float* e1 = g_eo + (size_t)p1 * LLM;
    float v[8];
    float sum = 0.f, sq = 0.f;
    #pragma unroll
    for (int i = 0; i < 8; i++) {
        int j = tid + i * 256;
        float val = sh[j] + e0[j] + e1[j];
        v[i] = val; sum += val; sq += val * val;
    }
    blockReduce2(sum, sq);
    float m = sum * (1.f / LLM);
    float var = sq * (1.f / LLM) - m * m;
    float rinv = rsqrtf(var + 1e-6f);
    float* orow = out + (size_t)t * LLM;
    #pragma unroll
    for (int i = 0; i < 8; i++) {
        int j = tid + i * 256;
        orow[j] = (v[i] - m) * rinv * lng[j] + lnb[j];
    }
}

// ---------------- launcher ----------------------------------------------------
extern "C" void kernel_launch(void* const* d_in, const int* in_sizes, int n_in,
                              void* d_out, int out_size)
{
    const float* x           = (const float*)d_in[0];
    const float* ln_pre_g    = (const float*)d_in[1];
    const float* ln_pre_b    = (const float*)d_in[2];
    const float* router_w    = (const float*)d_in[3];
    const float* router_b    = (const float*)d_in[4];
    const float* shared_w12  = (const float*)d_in[5];
    const float* shared_w3   = (const float*)d_in[6];
    const float* experts_w12 = (const float*)d_in[7];
    const float* experts_w3  = (const float*)d_in[8];
    const float* ln_post_g   = (const float*)d_in[9];
    const float* ln_post_b   = (const float*)d_in[10];
    float* out = (float*)d_out;

    cudaFuncSetAttribute(gemm12_mma, cudaFuncAttributeMaxDynamicSharedMemorySize, SMEM_DYN);
    cudaFuncSetAttribute(gemm3_mma,  cudaFuncAttributeMaxDynamicSharedMemorySize, SMEM_DYN);

    init_kernel<<<1, 32>>>();
    cvt_weights<<<4096, 256>>>((const float4*)shared_w12, (const float4*)shared_w3,
                               (const float4*)experts_w12, (const float4*)experts_w3);
    ln_router_kernel<<<T_TOK, 256>>>(x, ln_pre_g, ln_pre_b, router_w, router_b);
    scan_kernel<<<1, 32>>>();
    build_kernel<<<(T_TOK + 255) / 256, 256>>>();

    const int MT = (T_TOK + 127) / 128;   // 94 M-tiles (covers worst-case expert too)

    // shared branch
    gemm12_mma<<<dim3(HID / 64, MT, 1), 128, SMEM_DYN>>>(0);
    gemm3_mma <<<dim3(LLM / 128, MT, 1), 128, SMEM_DYN>>>(0);
    // expert branch (grouped over expert-sorted rows; empty tiles exit early)
    gemm12_mma<<<dim3(HID / 64, MT, NE), 128, SMEM_DYN>>>(1);
    gemm3_mma <<<dim3(LLM / 128, MT, NE), 128, SMEM_DYN>>>(1);

    ln_post_kernel<<<T_TOK, 256>>>(ln_post_g, ln_post_b, out);
}

// round 7
// speedup vs baseline: 3.9634x; 1.1423x over previous
#include <cuda_runtime.h>
#include <cuda_fp16.h>
#include <math.h>
#include <stdint.h>

// ---------------- problem constants ----------------------------------------
#define T_TOK 12000          // B*S/K tokens
#define D_IN  2560           // ENC*K
#define HID   512
#define LLM   2048
#define NE    8
#define NTOP  2
#define TWO   (T_TOK*NTOP)   // 24000 (token,slot) pairs

// ---------------- static device scratch ------------------------------------
__device__ __half g_nx[(size_t)T_TOK * D_IN];       // LN'd input (fp16, GEMM)
__device__ float  g_nx32[(size_t)T_TOK * D_IN];     // LN'd input (fp32, router)
__device__ __half g_act[(size_t)T_TOK * HID];       // shared swiglu (fp16)
__device__ float  g_shared[(size_t)T_TOK * LLM];
__device__ __half g_eact[(size_t)TWO * HID];        // expert swiglu (fp16)
__device__ float  g_eo[(size_t)TWO * LLM];
__device__ __half g_w12s[(size_t)2 * HID * D_IN];   // fp16 weights
__device__ __half g_w3s[(size_t)LLM * HID];
__device__ __half g_w12e[(size_t)NE * 2 * HID * D_IN];
__device__ __half g_w3e[(size_t)NE * LLM * HID];
__device__ int   g_idx[TWO];
__device__ float g_w[TWO];
__device__ int   g_perm[TWO];
__device__ float g_permw[TWO];
__device__ int   g_pos[TWO];
__device__ int   g_cnt[NE];
__device__ int   g_off[NE + 1];
__device__ int   g_cur[NE];

// ---------------- PTX helpers (sm_80-era; safe for plain sm_100) -----------
__device__ __forceinline__ uint32_t smem_u32(const void* p) {
    uint32_t a;
    asm("{ .reg .u64 t; cvta.to.shared.u64 t, %1; cvt.u32.u64 %0, t; }" : "=r"(a) : "l"(p));
    return a;
}
__device__ __forceinline__ void cpa16(uint32_t dst, const void* src, uint32_t srcsz) {
    asm volatile("cp.async.cg.shared.global [%0], [%1], 16, %2;"
                 :: "r"(dst), "l"(src), "r"(srcsz) : "memory");
}
#define CP_COMMIT() asm volatile("cp.async.commit_group;" ::: "memory")
#define CP_WAIT2()  asm volatile("cp.async.wait_group 2;" ::: "memory")

__device__ __forceinline__ void ldsm4(uint32_t& r0, uint32_t& r1, uint32_t& r2, uint32_t& r3,
                                      uint32_t addr) {
    asm volatile("ldmatrix.sync.aligned.m8n8.x4.shared.b16 {%0,%1,%2,%3}, [%4];"
                 : "=r"(r0), "=r"(r1), "=r"(r2), "=r"(r3) : "r"(addr));
}
__device__ __forceinline__ void mma_f16(float* c,
                                        uint32_t a0, uint32_t a1, uint32_t a2, uint32_t a3,
                                        uint32_t b0, uint32_t b1) {
    asm volatile(
        "mma.sync.aligned.m16n8k16.row.col.f32.f16.f16.f32 "
        "{%0,%1,%2,%3}, {%4,%5,%6,%7}, {%8,%9}, {%0,%1,%2,%3};"
        : "+f"(c[0]), "+f"(c[1]), "+f"(c[2]), "+f"(c[3])
        : "r"(a0), "r"(a1), "r"(a2), "r"(a3), "r"(b0), "r"(b1));
}

// ---------------- smem geometry ---------------------------------------------
// 144B row stride: 16B-group = (9*row + chunk) mod 8 -> conflict-free STS/ldsm.
#define ASTRB    144
#define A_BYTES  (128 * ASTRB)            // 18432
#define B_BYTES  (256 * ASTRB)            // 36864
#define STAGE_B  (A_BYTES + B_BYTES)      // 55296
#define SMEM_DYN (4 * STAGE_B)            // 221184, 4-stage pipeline
#define EPI_STR  264                      // fp32 epilogue stage stride

// ---------------- misc helpers ----------------------------------------------
__device__ __forceinline__ void blockReduce2(float& sum, float& sq) {
    __shared__ float ss[8], sv[8];
    #pragma unroll
    for (int o = 16; o > 0; o >>= 1) {
        sum += __shfl_down_sync(0xFFFFFFFFu, sum, o);
        sq  += __shfl_down_sync(0xFFFFFFFFu, sq,  o);
    }
    int w = threadIdx.x >> 5, l = threadIdx.x & 31;
    if (l == 0) { ss[w] = sum; sv[w] = sq; }
    __syncthreads();
    if (w == 0) {
        sum = (l < 8) ? ss[l] : 0.f;
        sq  = (l < 8) ? sv[l] : 0.f;
        #pragma unroll
        for (int o = 4; o > 0; o >>= 1) {
            sum += __shfl_down_sync(0xFFFFFFFFu, sum, o);
            sq  += __shfl_down_sync(0xFFFFFFFFu, sq,  o);
        }
        if (l == 0) { ss[0] = sum; sv[0] = sq; }
    }
    __syncthreads();
    sum = ss[0]; sq = sv[0];
}

// ---------------- kernel 0: zero counters -----------------------------------
__global__ void init_kernel() {
    int i = threadIdx.x;
    if (i < NE) { g_cnt[i] = 0; g_cur[i] = 0; }
}

// ---------------- kernel 0b: convert weights to fp16 ------------------------
__global__ __launch_bounds__(256) void cvt_weights(
    const float4* __restrict__ s12, const float4* __restrict__ s3,
    const float4* __restrict__ e12, const float4* __restrict__ e3)
{
    const int N1 = 2 * HID * D_IN / 4;
    const int N2 = LLM * HID / 4;
    const int N3 = NE * 2 * HID * D_IN / 4;
    const int N4 = NE * LLM * HID / 4;
    const int total = N1 + N2 + N3 + N4;
    for (int i = blockIdx.x * blockDim.x + threadIdx.x; i < total;
         i += gridDim.x * blockDim.x) {
        float4 v; __half2* dst;
        int j = i;
        if (j < N1)              { v = s12[j]; dst = (__half2*)g_w12s + 2 * j; }
        else if ((j -= N1) < N2) { v = s3[j];  dst = (__half2*)g_w3s  + 2 * j; }
        else if ((j -= N2) < N3) { v = e12[j]; dst = (__half2*)g_w12e + 2 * j; }
        else { j -= N3;           v = e3[j];  dst = (__half2*)g_w3e  + 2 * j; }
        dst[0] = __floats2half2_rn(v.x, v.y);
        dst[1] = __floats2half2_rn(v.z, v.w);
    }
}

// ---------------- kernel 1: LN_pre (writes fp16 for GEMM + fp32 for router) -
__global__ __launch_bounds__(256) void ln_pre_kernel(
    const float* __restrict__ x,
    const float* __restrict__ lng, const float* __restrict__ lnb)
{
    int t = blockIdx.x;
    const float* xr = x + (size_t)t * D_IN;
    int tid = threadIdx.x;
    float v[10];
    float sum = 0.f, sq = 0.f;
    #pragma unroll
    for (int i = 0; i < 10; i++) {
        v[i] = xr[tid + i * 256];
        sum += v[i]; sq += v[i] * v[i];
    }
    blockReduce2(sum, sq);
    float m = sum * (1.f / D_IN);
    float var = sq * (1.f / D_IN) - m * m;
    float rinv = rsqrtf(var + 1e-6f);
    __half* nxr = g_nx + (size_t)t * D_IN;
    float* nxr32 = g_nx32 + (size_t)t * D_IN;
    #pragma unroll
    for (int i = 0; i < 10; i++) {
        int j = tid + i * 256;
        float nv = (v[i] - m) * rinv * lng[j] + lnb[j];
        nxr32[j] = nv;                       // fp32: router fidelity
        nxr[j] = __float2half_rn(nv);        // fp16: GEMM operand
    }
}

// ---------------- kernel 2: tiled router (rw staged in smem, fp32 input) ----
__global__ __launch_bounds__(256) void router_kernel(
    const float* __restrict__ rw, const float* __restrict__ rb)
{
    extern __shared__ __align__(16) char smem[];
    float* s_rw = (float*)smem;                 // [NE][D_IN] fp32 = 80KB
    __shared__ int s_cnt[NE];
    int tid = threadIdx.x;
    if (tid < NE) s_cnt[tid] = 0;
    for (int i = tid; i < NE * D_IN / 4; i += 256)
        ((float4*)s_rw)[i] = ((const float4*)rw)[i];
    __syncthreads();

    int wid = tid >> 5, lane = tid & 31;
    for (int it = 0; it < 16; it++) {
        int t = blockIdx.x * 128 + wid * 16 + it;
        if (t >= T_TOK) break;
        const float2* row = (const float2*)(g_nx32 + (size_t)t * D_IN);
        float2 h[40];
        #pragma unroll
        for (int j = 0; j < 40; j++) h[j] = row[lane + j * 32];
        float lg[NE];
        #pragma unroll
        for (int e = 0; e < NE; e++) {
            const float2* w2 = (const float2*)(s_rw + e * D_IN);
            float acc = 0.f;
            #pragma unroll
            for (int j = 0; j < 40; j++) {
                float2 wv = w2[lane + j * 32];
                acc = fmaf(h[j].x, wv.x, acc);
                acc = fmaf(h[j].y, wv.y, acc);
            }
            #pragma unroll
            for (int o = 16; o > 0; o >>= 1)
                acc += __shfl_down_sync(0xFFFFFFFFu, acc, o);
            lg[e] = acc;
        }
        if (lane == 0) {
            float p[NE];
            float mx = lg[0] + rb[0];
            #pragma unroll
            for (int e = 0; e < NE; e++) { p[e] = lg[e] + rb[e]; mx = fmaxf(mx, p[e]); }
            float se = 0.f;
            #pragma unroll
            for (int e = 0; e < NE; e++) { p[e] = __expf(p[e] - mx); se += p[e]; }
            float rse = 1.f / se;
            #pragma unroll
            for (int e = 0; e < NE; e++) p[e] *= rse;
            int i0 = 0;
            #pragma unroll
            for (int e = 1; e < NE; e++) if (p[e] > p[i0]) i0 = e;
            int i1 = (i0 == 0) ? 1 : 0;
            #pragma unroll
            for (int e = 0; e < NE; e++) if (e != i0 && p[e] > p[i1]) i1 = e;
            float s2 = p[i0] + p[i1] + 1e-20f;
            g_idx[2 * t + 0] = i0; g_w[2 * t + 0] = p[i0] / s2;
            g_idx[2 * t + 1] = i1; g_w[2 * t + 1] = p[i1] / s2;
            atomicAdd(&s_cnt[i0], 1);
            atomicAdd(&s_cnt[i1], 1);
        }
    }
    __syncthreads();
    if (tid < NE && s_cnt[tid]) atomicAdd(&g_cnt[tid], s_cnt[tid]);
}

// ---------------- kernel 3/4: scan + permutation (aggregated atomics) -------
__global__ void scan_kernel() {
    if (threadIdx.x == 0) {
        int o = 0;
        for (int e = 0; e < NE; e++) { g_off[e] = o; o += g_cnt[e]; }
        g_off[NE] = o;
    }
}
__global__ __launch_bounds__(256) void build_kernel() {
    __shared__ int s_cur[NE], s_base[NE];
    int tid = threadIdx.x;
    if (tid < NE) s_cur[tid] = 0;
    __syncthreads();
    int t = blockIdx.x * 256 + tid;
    int e2[2], lp[2];
    if (t < T_TOK) {
        #pragma unroll
        for (int k = 0; k < NTOP; k++) {
            e2[k] = g_idx[2 * t + k];
            lp[k] = atomicAdd(&s_cur[e2[k]], 1);
        }
    }
    __syncthreads();
    if (tid < NE) s_base[tid] = s_cur[tid] ? atomicAdd(&g_cur[tid], s_cur[tid]) : 0;
    __syncthreads();
    if (t < T_TOK) {
        #pragma unroll
        for (int k = 0; k < NTOP; k++) {
            int p = g_off[e2[k]] + s_base[e2[k]] + lp[k];
            g_perm[p]  = t;
            g_permw[p] = g_w[2 * t + k];
            g_pos[2 * t + k] = p;
        }
    }
}

// ============================================================================
// fp16 mma core: CTA 128x256, BK=64, 256 threads, 8 warps (2x4), warp 64x64
// ============================================================================
#define GEMM_FRAGS                                                            \
    const int lane = threadIdx.x & 31, wid = threadIdx.x >> 5;                \
    const int wm = (wid >> 2) * 64, wn = (wid & 3) * 64;                      \
    const int l16 = lane & 15, lh = lane >> 4;                                \
    const int bg = lane >> 3;                                                 \
    const int b_row = ((bg & 1) << 3) + (lane & 7), b_ch = bg >> 1;

#define GEMM_KSTEP(abase, bbase)                                              \
    _Pragma("unroll")                                                         \
    for (int step = 0; step < 4; step++) {                                    \
        uint32_t a[4][4], b[4][4];                                            \
        _Pragma("unroll")                                                     \
        for (int mf = 0; mf < 4; mf++)                                        \
            ldsm4(a[mf][0], a[mf][1], a[mf][2], a[mf][3],                     \
                  (abase) + (wm + mf * 16 + l16) * ASTRB + (step * 2 + lh) * 16); \
        _Pragma("unroll")                                                     \
        for (int nb = 0; nb < 4; nb++)                                        \
            ldsm4(b[nb][0], b[nb][1], b[nb][2], b[nb][3],                     \
                  (bbase) + (wn + nb * 16 + b_row) * ASTRB + (step * 2 + b_ch) * 16); \
        _Pragma("unroll")                                                     \
        for (int mf = 0; mf < 4; mf++)                                        \
            _Pragma("unroll")                                                 \
            for (int nb = 0; nb < 4; nb++) {                                  \
                mma_f16(acc[mf][2 * nb],     a[mf][0], a[mf][1], a[mf][2], a[mf][3], b[nb][0], b[nb][2]); \
                mma_f16(acc[mf][2 * nb + 1], a[mf][0], a[mf][1], a[mf][2], a[mf][3], b[nb][1], b[nb][3]); \
            }                                                                 \
    }

#define GEMM_EPI_STAGE(st)                                                    \
    {                                                                         \
        const int cg = lane >> 2, ct = lane & 3;                              \
        _Pragma("unroll")                                                     \
        for (int mf = 0; mf < 4; mf++) {                                      \
            int row = wm + mf * 16 + cg;                                      \
            _Pragma("unroll")                                                 \
            for (int nf = 0; nf < 8; nf++) {                                  \
                int col = wn + nf * 8 + ct * 2;                               \
                *(float2*)((st) + row * EPI_STR + col)       = make_float2(acc[mf][nf][0], acc[mf][nf][1]); \
                *(float2*)((st) + (row + 8) * EPI_STR + col) = make_float2(acc[mf][nf][2], acc[mf][nf][3]); \
            }                                                                 \
        }                                                                     \
    }

// ============================================================================
// kernel 5: GEMM w12 + fused SwiGLU, merged shared(z=0)/expert(z=1..8)
//   CTA computes 128 rows x 128 act cols (256 w12 rows: 128 gate + 128 val)
// ============================================================================
__global__ __launch_bounds__(256, 1) void gemm12_mma()
{
    const int z = blockIdx.z;
    int rowStart, nrows;
    const __half* W;
    if (z == 0) {
        rowStart = blockIdx.y * 128;
        if (rowStart >= T_TOK) return;
        nrows = min(128, T_TOK - rowStart);
        W = g_w12s;
    } else {
        int e = z - 1;
        int re = g_off[e + 1];
        rowStart = g_off[e] + blockIdx.y * 128;
        if (rowStart >= re) return;
        nrows = min(128, re - rowStart);
        W = g_w12e + (size_t)e * (2 * HID) * D_IN;
    }
    const int colBase = blockIdx.x * 128;   // act column tile

    extern __shared__ __align__(16) char smem[];
    __shared__ int s_perm[128];
    const uint32_t sbase = smem_u32(smem);
    const int tid = threadIdx.x;

    if (z && tid < 128)
        s_perm[tid] = (tid < nrows) ? g_perm[rowStart + tid] : 0;
    __syncthreads();

    const int arow = tid >> 1;
    const uint32_t avalid = (arow < nrows) ? 16 : 0;
    const __half* srcA = (z ? (g_nx + (size_t)s_perm[arow] * D_IN)
                            : (g_nx + (size_t)(rowStart + min(arow, nrows - 1)) * D_IN))
                         + (tid & 1) * 32;
    const int wrow = (tid < 128) ? (colBase + tid) : (HID + colBase + (tid - 128));
    const __half* srcB = W + (size_t)wrow * D_IN;
    const uint32_t adst0 = sbase + arow * ASTRB + (tid & 1) * 64;
    const uint32_t bdst0 = sbase + A_BYTES + tid * ASTRB;

    auto fill = [&](int s, int k0) {
        uint32_t ad = adst0 + s * STAGE_B;
        #pragma unroll
        for (int j = 0; j < 4; j++) cpa16(ad + j * 16, srcA + k0 + j * 8, avalid);
        uint32_t bd = bdst0 + s * STAGE_B;
        #pragma unroll
        for (int j = 0; j < 8; j++) cpa16(bd + j * 16, srcB + k0 + j * 8, 16);
        CP_COMMIT();
    };

    fill(0, 0); fill(1, 64); fill(2, 128);

    float acc[4][8][4] = {};
    GEMM_FRAGS

    const int NK = D_IN / 64;   // 40
    for (int kt = 0; kt < NK; kt++) {
        CP_WAIT2();
        __syncthreads();
        if (kt + 3 < NK) fill((kt + 3) & 3, (kt + 3) * 64);
        else CP_COMMIT();       // keep pending-group count aligned
        uint32_t abase = sbase + (kt & 3) * STAGE_B;
        GEMM_KSTEP(abase, abase + A_BYTES)
    }
    __syncthreads();

    float* st = (float*)smem;   // [128][EPI_STR]
    GEMM_EPI_STAGE(st)
    __syncthreads();

    __half* Out = z ? g_eact : g_act;
    #pragma unroll
    for (int i = 0; i < 16; i++) {
        int f = tid + i * 256;
        int r = f >> 5, c4 = f & 31;            // 32 x 4-half chunks = 128 cols
        if (r < nrows) {
            float4 gg = *(float4*)(st + r * EPI_STR + c4 * 4);
            float4 vv = *(float4*)(st + r * EPI_STR + 128 + c4 * 4);
            __half2 h0 = __floats2half2_rn(gg.x / (1.f + __expf(-gg.x)) * vv.x,
                                           gg.y / (1.f + __expf(-gg.y)) * vv.y);
            __half2 h1 = __floats2half2_rn(gg.z / (1.f + __expf(-gg.z)) * vv.z,
                                           gg.w / (1.f + __expf(-gg.w)) * vv.w);
            uint32_t u0 = *(uint32_t*)&h0, u1 = *(uint32_t*)&h1;
            *(uint2*)(Out + (size_t)(rowStart + r) * HID + colBase + c4 * 4) =
                make_uint2(u0, u1);
        }
    }
}

// ============================================================================
// kernel 6: GEMM w3 (+ fused routing weight), merged z, K=512
//   CTA computes 128 rows x 256 out cols
// ============================================================================
__global__ __launch_bounds__(256, 1) void gemm3_mma()
{
    const int z = blockIdx.z;
    int rowStart, nrows;
    const __half* W;
    if (z == 0) {
        rowStart = blockIdx.y * 128;
        if (rowStart >= T_TOK) return;
        nrows = min(128, T_TOK - rowStart);
        W = g_w3s;
    } else {
        int e = z - 1;
        int re = g_off[e + 1];
        rowStart = g_off[e] + blockIdx.y * 128;
        if (rowStart >= re) return;
        nrows = min(128, re - rowStart);
        W = g_w3e + (size_t)e * LLM * HID;
    }
    const int colBase = blockIdx.x * 256;
    const __half* Act = z ? g_eact : g_act;

    extern __shared__ __align__(16) char smem[];
    const uint32_t sbase = smem_u32(smem);
    const int tid = threadIdx.x;

    const int arow = tid >> 1;
    const uint32_t avalid = (arow < nrows) ? 16 : 0;
    const __half* srcA = Act + (size_t)(rowStart + min(arow, nrows - 1)) * HID + (tid & 1) * 32;
    const __half* srcB = W + (size_t)(colBase + tid) * HID;
    const uint32_t adst0 = sbase + arow * ASTRB + (tid & 1) * 64;
    const uint32_t bdst0 = sbase + A_BYTES + tid * ASTRB;

    auto fill = [&](int s, int k0) {
        uint32_t ad = adst0 + s * STAGE_B;
        #pragma unroll
        for (int j = 0; j < 4; j++) cpa16(ad + j * 16, srcA + k0 + j * 8, avalid);
        uint32_t bd = bdst0 + s * STAGE_B;
        #pragma unroll
        for (int j = 0; j < 8; j++) cpa16(bd + j * 16, srcB + k0 + j * 8, 16);
        CP_COMMIT();
    };

    fill(0, 0); fill(1, 64); fill(2, 128);

    float acc[4][8][4] = {};
    GEMM_FRAGS

    const int NK = HID / 64;    // 8
    for (int kt = 0; kt < NK; kt++) {
        CP_WAIT2();
        __syncthreads();
        if (kt + 3 < NK) fill((kt + 3) & 3, (kt + 3) * 64);
        else CP_COMMIT();
        uint32_t abase = sbase + (kt & 3) * STAGE_B;
        GEMM_KSTEP(abase, abase + A_BYTES)
    }
    __syncthreads();

    float* st = (float*)smem;   // [128][EPI_STR]
    GEMM_EPI_STAGE(st)
    __syncthreads();

    float* Out = z ? g_eo : g_shared;
    #pragma unroll
    for (int i = 0; i < 32; i++) {
        int f = tid + i * 256;
        int r = f >> 6, c4 = f & 63;            // 64 x float4 = 256 cols
        if (r < nrows) {
            float sc = z ? g_permw[rowStart + r] : 1.f;
            float4 v = *(float4*)(st + r * EPI_STR + c4 * 4);
            v.x *= sc; v.y *= sc; v.z *= sc; v.w *= sc;
            *(float4*)(Out + (size_t)(rowStart + r) * LLM + colBase + c4 * 4) = v;
        }
    }
}

// ---------------- kernel 7: combine + LN_post --------------------------------
__global__ __launch_bounds__(256) void ln_post_kernel(
    const float* __restrict__ lng, const float* __restrict__ lnb,
    float* __restrict__ out)
{
    int t = blockIdx.x;
    int tid = threadIdx.x;
    int p0 = g_pos[2 * t + 0], p1 = g_pos[2 * t + 1];
    const float* sh = g_shared + (size_t)t * LLM;
    const float* e0 = g_eo + (size_t)p0 * LLM;
    const float* e1 = g_eo + (size_t)p1 * LLM;
    float v[8];
    float sum = 0.f, sq = 0.f;
    #pragma unroll
    for (int i = 0; i < 8; i++) {
        int j = tid + i * 256;
        float val = sh[j] + e0[j] + e1[j];
        v[i] = val; sum += val; sq += val * val;
    }
    blockReduce2(sum, sq);
    float m = sum * (1.f / LLM);
    float var = sq * (1.f / LLM) - m * m;
    float rinv = rsqrtf(var + 1e-6f);
    float* orow = out + (size_t)t * LLM;
    #pragma unroll
    for (int i = 0; i < 8; i++) {
        int j = tid + i * 256;
        orow[j] = (v[i] - m) * rinv * lng[j] + lnb[j];
    }
}

// ---------------- launcher ----------------------------------------------------
extern "C" void kernel_launch(void* const* d_in, const int* in_sizes, int n_in,
                              void* d_out, int out_size)
{
    const float* x           = (const float*)d_in[0];
    const float* ln_pre_g    = (const float*)d_in[1];
    const float* ln_pre_b    = (const float*)d_in[2];
    const float* router_w    = (const float*)d_in[3];
    const float* router_b    = (const float*)d_in[4];
    const float* shared_w12  = (const float*)d_in[5];
    const float* shared_w3   = (const float*)d_in[6];
    const float* experts_w12 = (const float*)d_in[7];
    const float* experts_w3  = (const float*)d_in[8];
    const float* ln_post_g   = (const float*)d_in[9];
    const float* ln_post_b   = (const float*)d_in[10];
    float* out = (float*)d_out;

    const int RW_SMEM = NE * D_IN * 4;  // 80 KB
    cudaFuncSetAttribute(gemm12_mma, cudaFuncAttributeMaxDynamicSharedMemorySize, SMEM_DYN);
    cudaFuncSetAttribute(gemm3_mma,  cudaFuncAttributeMaxDynamicSharedMemorySize, SMEM_DYN);
    cudaFuncSetAttribute(router_kernel, cudaFuncAttributeMaxDynamicSharedMemorySize, RW_SMEM);

    init_kernel<<<1, 32>>>();
    cvt_weights<<<4096, 256>>>((const float4*)shared_w12, (const float4*)shared_w3,
                               (const float4*)experts_w12, (const float4*)experts_w3);
    ln_pre_kernel<<<T_TOK, 256>>>(x, ln_pre_g, ln_pre_b);
    router_kernel<<<(T_TOK + 127) / 128, 256, RW_SMEM>>>(router_w, router_b);
    scan_kernel<<<1, 32>>>();
    build_kernel<<<(T_TOK + 255) / 256, 256>>>();

    const int MT = (T_TOK + 127) / 128;   // 94 (also covers worst-case expert)
    gemm12_mma<<<dim3(HID / 128, MT, NE + 1), 256, SMEM_DYN>>>();
    gemm3_mma <<<dim3(LLM / 256, MT, NE + 1), 256, SMEM_DYN>>>();

    ln_post_kernel<<<T_TOK, 256>>>(ln_post_g, ln_post_b, out);
}

// round 8
// speedup vs baseline: 4.1424x; 1.0452x over previous
#include <cuda_runtime.h>
#include <cuda_fp16.h>
#include <math.h>
#include <stdint.h>

// ---------------- problem constants ----------------------------------------
#define T_TOK 12000          // B*S/K tokens
#define D_IN  2560           // ENC*K
#define HID   512
#define LLM   2048
#define NE    8
#define NTOP  2
#define TWO   (T_TOK*NTOP)   // 24000 (token,slot) pairs

// ---------------- static device scratch ------------------------------------
__device__ __half g_nx[(size_t)T_TOK * D_IN];       // LN'd input (fp16, GEMM)
__device__ float  g_nx32[(size_t)T_TOK * D_IN];     // LN'd input (fp32, router)
__device__ __half g_act[(size_t)T_TOK * HID];       // shared swiglu (fp16)
__device__ __half g_shared[(size_t)T_TOK * LLM];    // shared out (fp16)
__device__ __half g_eact[(size_t)TWO * HID];        // expert swiglu (fp16)
__device__ __half g_eo[(size_t)TWO * LLM];          // expert out (fp16)
__device__ __half g_w12s[(size_t)2 * HID * D_IN];   // fp16 weights
__device__ __half g_w3s[(size_t)LLM * HID];
__device__ __half g_w12e[(size_t)NE * 2 * HID * D_IN];
__device__ __half g_w3e[(size_t)NE * LLM * HID];
__device__ int   g_idx[TWO];
__device__ float g_w[TWO];
__device__ int   g_perm[TWO];
__device__ float g_permw[TWO];
__device__ int   g_pos[TWO];
__device__ int   g_cnt[NE];
__device__ int   g_off[NE + 1];
__device__ int   g_cur[NE];

// ---------------- PTX helpers (sm_80-era; safe for plain sm_100) -----------
__device__ __forceinline__ uint32_t smem_u32(const void* p) {
    uint32_t a;
    asm("{ .reg .u64 t; cvta.to.shared.u64 t, %1; cvt.u32.u64 %0, t; }" : "=r"(a) : "l"(p));
    return a;
}
__device__ __forceinline__ void cpa16(uint32_t dst, const void* src, uint32_t srcsz) {
    asm volatile("cp.async.cg.shared.global [%0], [%1], 16, %2;"
                 :: "r"(dst), "l"(src), "r"(srcsz) : "memory");
}
#define CP_COMMIT() asm volatile("cp.async.commit_group;" ::: "memory")
#define CP_WAIT2()  asm volatile("cp.async.wait_group 2;" ::: "memory")

__device__ __forceinline__ void ldsm4(uint32_t& r0, uint32_t& r1, uint32_t& r2, uint32_t& r3,
                                      uint32_t addr) {
    asm volatile("ldmatrix.sync.aligned.m8n8.x4.shared.b16 {%0,%1,%2,%3}, [%4];"
                 : "=r"(r0), "=r"(r1), "=r"(r2), "=r"(r3) : "r"(addr));
}
__device__ __forceinline__ void mma_f16(float* c,
                                        uint32_t a0, uint32_t a1, uint32_t a2, uint32_t a3,
                                        uint32_t b0, uint32_t b1) {
    asm volatile(
        "mma.sync.aligned.m16n8k16.row.col.f32.f16.f16.f32 "
        "{%0,%1,%2,%3}, {%4,%5,%6,%7}, {%8,%9}, {%0,%1,%2,%3};"
        : "+f"(c[0]), "+f"(c[1]), "+f"(c[2]), "+f"(c[3])
        : "r"(a0), "r"(a1), "r"(a2), "r"(a3), "r"(b0), "r"(b1));
}

// ---------------- smem geometry ---------------------------------------------
#define ASTRB    144
#define A_BYTES  (128 * ASTRB)            // 18432
#define B_BYTES  (256 * ASTRB)            // 36864
#define STAGE_B  (A_BYTES + B_BYTES)      // 55296
#define SMEM_DYN (4 * STAGE_B)            // 221184, 4-stage pipeline
#define EPI_STR  264                      // fp32 epilogue stage stride

// ---------------- misc helpers ----------------------------------------------
__device__ __forceinline__ void blockReduce2(float& sum, float& sq) {
    __shared__ float ss[8], sv[8];
    #pragma unroll
    for (int o = 16; o > 0; o >>= 1) {
        sum += __shfl_down_sync(0xFFFFFFFFu, sum, o);
        sq  += __shfl_down_sync(0xFFFFFFFFu, sq,  o);
    }
    int w = threadIdx.x >> 5, l = threadIdx.x & 31;
    if (l == 0) { ss[w] = sum; sv[w] = sq; }
    __syncthreads();
    if (w == 0) {
        sum = (l < 8) ? ss[l] : 0.f;
        sq  = (l < 8) ? sv[l] : 0.f;
        #pragma unroll
        for (int o = 4; o > 0; o >>= 1) {
            sum += __shfl_down_sync(0xFFFFFFFFu, sum, o);
            sq  += __shfl_down_sync(0xFFFFFFFFu, sq,  o);
        }
        if (l == 0) { ss[0] = sum; sv[0] = sq; }
    }
    __syncthreads();
    sum = ss[0]; sq = sv[0];
}

// ---------------- kernel 0: convert weights to fp16 (+ zero counters) -------
__global__ __launch_bounds__(256) void cvt_weights(
    const float4* __restrict__ s12, const float4* __restrict__ s3,
    const float4* __restrict__ e12, const float4* __restrict__ e3)
{
    if (blockIdx.x == 0 && threadIdx.x < NE) {
        g_cnt[threadIdx.x] = 0;
        g_cur[threadIdx.x] = 0;
    }
    const int N1 = 2 * HID * D_IN / 4;
    const int N2 = LLM * HID / 4;
    const int N3 = NE * 2 * HID * D_IN / 4;
    const int N4 = NE * LLM * HID / 4;
    const int total = N1 + N2 + N3 + N4;
    for (int i = blockIdx.x * blockDim.x + threadIdx.x; i < total;
         i += gridDim.x * blockDim.x) {
        float4 v; __half2* dst;
        int j = i;
        if (j < N1)              { v = s12[j]; dst = (__half2*)g_w12s + 2 * j; }
        else if ((j -= N1) < N2) { v = s3[j];  dst = (__half2*)g_w3s  + 2 * j; }
        else if ((j -= N2) < N3) { v = e12[j]; dst = (__half2*)g_w12e + 2 * j; }
        else { j -= N3;           v = e3[j];  dst = (__half2*)g_w3e  + 2 * j; }
        dst[0] = __floats2half2_rn(v.x, v.y);
        dst[1] = __floats2half2_rn(v.z, v.w);
    }
}

// ---------------- kernel 1: LN_pre (fp16 for GEMM + fp32 for router) --------
__global__ __launch_bounds__(256) void ln_pre_kernel(
    const float* __restrict__ x,
    const float* __restrict__ lng, const float* __restrict__ lnb)
{
    int t = blockIdx.x;
    const float* xr = x + (size_t)t * D_IN;
    int tid = threadIdx.x;
    float v[10];
    float sum = 0.f, sq = 0.f;
    #pragma unroll
    for (int i = 0; i < 10; i++) {
        v[i] = xr[tid + i * 256];
        sum += v[i]; sq += v[i] * v[i];
    }
    blockReduce2(sum, sq);
    float m = sum * (1.f / D_IN);
    float var = sq * (1.f / D_IN) - m * m;
    float rinv = rsqrtf(var + 1e-6f);
    __half* nxr = g_nx + (size_t)t * D_IN;
    float* nxr32 = g_nx32 + (size_t)t * D_IN;
    #pragma unroll
    for (int i = 0; i < 10; i++) {
        int j = tid + i * 256;
        float nv = (v[i] - m) * rinv * lng[j] + lnb[j];
        nxr32[j] = nv;                       // fp32: router fidelity
        nxr[j] = __float2half_rn(nv);        // fp16: GEMM operand
    }
}

// ---------------- kernel 2: tiled router (rw staged in smem, fp32 input) ----
__global__ __launch_bounds__(256) void router_kernel(
    const float* __restrict__ rw, const float* __restrict__ rb)
{
    extern __shared__ __align__(16) char smem[];
    float* s_rw = (float*)smem;                 // [NE][D_IN] fp32 = 80KB
    __shared__ int s_cnt[NE];
    int tid = threadIdx.x;
    if (tid < NE) s_cnt[tid] = 0;
    for (int i = tid; i < NE * D_IN / 4; i += 256)
        ((float4*)s_rw)[i] = ((const float4*)rw)[i];
    __syncthreads();

    int wid = tid >> 5, lane = tid & 31;
    for (int it = 0; it < 16; it++) {
        int t = blockIdx.x * 128 + wid * 16 + it;
        if (t >= T_TOK) break;
        const float2* row = (const float2*)(g_nx32 + (size_t)t * D_IN);
        float2 h[40];
        #pragma unroll
        for (int j = 0; j < 40; j++) h[j] = row[lane + j * 32];
        float lg[NE];
        #pragma unroll
        for (int e = 0; e < NE; e++) {
            const float2* w2 = (const float2*)(s_rw + e * D_IN);
            float acc = 0.f;
            #pragma unroll
            for (int j = 0; j < 40; j++) {
                float2 wv = w2[lane + j * 32];
                acc = fmaf(h[j].x, wv.x, acc);
                acc = fmaf(h[j].y, wv.y, acc);
            }
            #pragma unroll
            for (int o = 16; o > 0; o >>= 1)
                acc += __shfl_down_sync(0xFFFFFFFFu, acc, o);
            lg[e] = acc;
        }
        if (lane == 0) {
            float p[NE];
            float mx = lg[0] + rb[0];
            #pragma unroll
            for (int e = 0; e < NE; e++) { p[e] = lg[e] + rb[e]; mx = fmaxf(mx, p[e]); }
            float se = 0.f;
            #pragma unroll
            for (int e = 0; e < NE; e++) { p[e] = __expf(p[e] - mx); se += p[e]; }
            float rse = 1.f / se;
            #pragma unroll
            for (int e = 0; e < NE; e++) p[e] *= rse;
            int i0 = 0;
            #pragma unroll
            for (int e = 1; e < NE; e++) if (p[e] > p[i0]) i0 = e;
            int i1 = (i0 == 0) ? 1 : 0;
            #pragma unroll
            for (int e = 0; e < NE; e++) if (e != i0 && p[e] > p[i1]) i1 = e;
            float s2 = p[i0] + p[i1] + 1e-20f;
            g_idx[2 * t + 0] = i0; g_w[2 * t + 0] = p[i0] / s2;
            g_idx[2 * t + 1] = i1; g_w[2 * t + 1] = p[i1] / s2;
            atomicAdd(&s_cnt[i0], 1);
            atomicAdd(&s_cnt[i1], 1);
        }
    }
    __syncthreads();
    if (tid < NE && s_cnt[tid]) atomicAdd(&g_cnt[tid], s_cnt[tid]);
}

// ---------------- kernel 3/4: scan + permutation (aggregated atomics) -------
__global__ void scan_kernel() {
    if (threadIdx.x == 0) {
        int o = 0;
        for (int e = 0; e < NE; e++) { g_off[e] = o; o += g_cnt[e]; }
        g_off[NE] = o;
    }
}
__global__ __launch_bounds__(256) void build_kernel() {
    __shared__ int s_cur[NE], s_base[NE];
    int tid = threadIdx.x;
    if (tid < NE) s_cur[tid] = 0;
    __syncthreads();
    int t = blockIdx.x * 256 + tid;
    int e2[2], lp[2];
    if (t < T_TOK) {
        #pragma unroll
        for (int k = 0; k < NTOP; k++) {
            e2[k] = g_idx[2 * t + k];
            lp[k] = atomicAdd(&s_cur[e2[k]], 1);
        }
    }
    __syncthreads();
    if (tid < NE) s_base[tid] = s_cur[tid] ? atomicAdd(&g_cur[tid], s_cur[tid]) : 0;
    __syncthreads();
    if (t < T_TOK) {
        #pragma unroll
        for (int k = 0; k < NTOP; k++) {
            int p = g_off[e2[k]] + s_base[e2[k]] + lp[k];
            g_perm[p]  = t;
            g_permw[p] = g_w[2 * t + k];
            g_pos[2 * t + k] = p;
        }
    }
}

// ============================================================================
// fp16 mma core: CTA 128x256, BK=64, 256 threads, 8 warps (2x4), warp 64x64
// Register double-buffered fragment pipeline inside each k-tile.
// ============================================================================
#define GEMM_FRAGS                                                            \
    const int lane = threadIdx.x & 31, wid = threadIdx.x >> 5;                \
    const int wm = (wid >> 2) * 64, wn = (wid & 3) * 64;                      \
    const int l16 = lane & 15, lh = lane >> 4;                                \
    const int bg = lane >> 3;                                                 \
    const int b_row = ((bg & 1) << 3) + (lane & 7), b_ch = bg >> 1;

#define LOAD_FRAGS(A, B, abase, bbase, step)                                  \
    _Pragma("unroll")                                                         \
    for (int mf = 0; mf < 4; mf++)                                            \
        ldsm4((A)[mf][0], (A)[mf][1], (A)[mf][2], (A)[mf][3],                 \
              (abase) + (wm + mf * 16 + l16) * ASTRB + ((step) * 2 + lh) * 16); \
    _Pragma("unroll")                                                         \
    for (int nb = 0; nb < 4; nb++)                                            \
        ldsm4((B)[nb][0], (B)[nb][1], (B)[nb][2], (B)[nb][3],                 \
              (bbase) + (wn + nb * 16 + b_row) * ASTRB + ((step) * 2 + b_ch) * 16);

#define MMA_FRAGS(A, B)                                                       \
    _Pragma("unroll")                                                         \
    for (int mf = 0; mf < 4; mf++)                                            \
        _Pragma("unroll")                                                     \
        for (int nb = 0; nb < 4; nb++) {                                      \
            mma_f16(acc[mf][2 * nb],     (A)[mf][0], (A)[mf][1], (A)[mf][2], (A)[mf][3], (B)[nb][0], (B)[nb][2]); \
            mma_f16(acc[mf][2 * nb + 1], (A)[mf][0], (A)[mf][1], (A)[mf][2], (A)[mf][3], (B)[nb][1], (B)[nb][3]); \
        }

#define GEMM_MAINLOOP(NK)                                                     \
    uint32_t af[2][4][4], bf[2][4][4];                                        \
    for (int kt = 0; kt < (NK); kt++) {                                       \
        CP_WAIT2();                                                           \
        __syncthreads();                                                      \
        uint32_t abase = sbase + (kt & 3) * STAGE_B;                          \
        uint32_t bbase = abase + A_BYTES;                                     \
        LOAD_FRAGS(af[0], bf[0], abase, bbase, 0)                             \
        if (kt + 3 < (NK)) fill((kt + 3) & 3, (kt + 3) * 64);                 \
        else CP_COMMIT();                                                     \
        _Pragma("unroll")                                                     \
        for (int step = 0; step < 4; step++) {                                \
            if (step < 3) { LOAD_FRAGS(af[(step + 1) & 1], bf[(step + 1) & 1], abase, bbase, step + 1) } \
            MMA_FRAGS(af[step & 1], bf[step & 1])                             \
        }                                                                     \
    }

#define GEMM_EPI_STAGE(st)                                                    \
    {                                                                         \
        const int cg = lane >> 2, ct = lane & 3;                              \
        _Pragma("unroll")                                                     \
        for (int mf = 0; mf < 4; mf++) {                                      \
            int row = wm + mf * 16 + cg;                                      \
            _Pragma("unroll")                                                 \
            for (int nf = 0; nf < 8; nf++) {                                  \
                int col = wn + nf * 8 + ct * 2;                               \
                *(float2*)((st) + row * EPI_STR + col)       = make_float2(acc[mf][nf][0], acc[mf][nf][1]); \
                *(float2*)((st) + (row + 8) * EPI_STR + col) = make_float2(acc[mf][nf][2], acc[mf][nf][3]); \
            }                                                                 \
        }                                                                     \
    }

// ============================================================================
// kernel 5: GEMM w12 + fused SwiGLU, merged shared(z=0)/expert(z=1..8)
// ============================================================================
__global__ __launch_bounds__(256, 1) void gemm12_mma()
{
    const int z = blockIdx.z;
    int rowStart, nrows;
    const __half* W;
    if (z == 0) {
        rowStart = blockIdx.y * 128;
        if (rowStart >= T_TOK) return;
        nrows = min(128, T_TOK - rowStart);
        W = g_w12s;
    } else {
        int e = z - 1;
        int re = g_off[e + 1];
        rowStart = g_off[e] + blockIdx.y * 128;
        if (rowStart >= re) return;
        nrows = min(128, re - rowStart);
        W = g_w12e + (size_t)e * (2 * HID) * D_IN;
    }
    const int colBase = blockIdx.x * 128;   // act column tile

    extern __shared__ __align__(16) char smem[];
    __shared__ int s_perm[128];
    const uint32_t sbase = smem_u32(smem);
    const int tid = threadIdx.x;

    if (z && tid < 128)
        s_perm[tid] = (tid < nrows) ? g_perm[rowStart + tid] : 0;
    __syncthreads();

    const int arow = tid >> 1;
    const uint32_t avalid = (arow < nrows) ? 16 : 0;
    const __half* srcA = (z ? (g_nx + (size_t)s_perm[arow] * D_IN)
                            : (g_nx + (size_t)(rowStart + min(arow, nrows - 1)) * D_IN))
                         + (tid & 1) * 32;
    const int wrow = (tid < 128) ? (colBase + tid) : (HID + colBase + (tid - 128));
    const __half* srcB = W + (size_t)wrow * D_IN;
    const uint32_t adst0 = sbase + arow * ASTRB + (tid & 1) * 64;
    const uint32_t bdst0 = sbase + A_BYTES + tid * ASTRB;

    auto fill = [&](int s, int k0) {
        uint32_t ad = adst0 + s * STAGE_B;
        #pragma unroll
        for (int j = 0; j < 4; j++) cpa16(ad + j * 16, srcA + k0 + j * 8, avalid);
        uint32_t bd = bdst0 + s * STAGE_B;
        #pragma unroll
        for (int j = 0; j < 8; j++) cpa16(bd + j * 16, srcB + k0 + j * 8, 16);
        CP_COMMIT();
    };

    fill(0, 0); fill(1, 64); fill(2, 128);

    float acc[4][8][4] = {};
    GEMM_FRAGS
    GEMM_MAINLOOP(D_IN / 64)
    __syncthreads();

    float* st = (float*)smem;   // [128][EPI_STR]
    GEMM_EPI_STAGE(st)
    __syncthreads();

    __half* Out = z ? g_eact : g_act;
    #pragma unroll
    for (int i = 0; i < 16; i++) {
        int f = tid + i * 256;
        int r = f >> 5, c4 = f & 31;            // 32 x 4-half chunks = 128 cols
        if (r < nrows) {
            float4 gg = *(float4*)(st + r * EPI_STR + c4 * 4);
            float4 vv = *(float4*)(st + r * EPI_STR + 128 + c4 * 4);
            __half2 h0 = __floats2half2_rn(gg.x / (1.f + __expf(-gg.x)) * vv.x,
                                           gg.y / (1.f + __expf(-gg.y)) * vv.y);
            __half2 h1 = __floats2half2_rn(gg.z / (1.f + __expf(-gg.z)) * vv.z,
                                           gg.w / (1.f + __expf(-gg.w)) * vv.w);
            uint32_t u0 = *(uint32_t*)&h0, u1 = *(uint32_t*)&h1;
            *(uint2*)(Out + (size_t)(rowStart + r) * HID + colBase + c4 * 4) =
                make_uint2(u0, u1);
        }
    }
}

// ============================================================================
// kernel 6: GEMM w3 (+ fused routing weight), merged z, K=512, fp16 output
// ============================================================================
__global__ __launch_bounds__(256, 1) void gemm3_mma()
{
    const int z = blockIdx.z;
    int rowStart, nrows;
    const __half* W;
    if (z == 0) {
        rowStart = blockIdx.y * 128;
        if (rowStart >= T_TOK) return;
        nrows = min(128, T_TOK - rowStart);
        W = g_w3s;
    } else {
        int e = z - 1;
        int re = g_off[e + 1];
        rowStart = g_off[e] + blockIdx.y * 128;
        if (rowStart >= re) return;
        nrows = min(128, re - rowStart);
        W = g_w3e + (size_t)e * LLM * HID;
    }
    const int colBase = blockIdx.x * 256;
    const __half* Act = z ? g_eact : g_act;

    extern __shared__ __align__(16) char smem[];
    const uint32_t sbase = smem_u32(smem);
    const int tid = threadIdx.x;

    const int arow = tid >> 1;
    const uint32_t avalid = (arow < nrows) ? 16 : 0;
    const __half* srcA = Act + (size_t)(rowStart + min(arow, nrows - 1)) * HID + (tid & 1) * 32;
    const __half* srcB = W + (size_t)(colBase + tid) * HID;
    const uint32_t adst0 = sbase + arow * ASTRB + (tid & 1) * 64;
    const uint32_t bdst0 = sbase + A_BYTES + tid * ASTRB;

    auto fill = [&](int s, int k0) {
        uint32_t ad = adst0 + s * STAGE_B;
        #pragma unroll
        for (int j = 0; j < 4; j++) cpa16(ad + j * 16, srcA + k0 + j * 8, avalid);
        uint32_t bd = bdst0 + s * STAGE_B;
        #pragma unroll
        for (int j = 0; j < 8; j++) cpa16(bd + j * 16, srcB + k0 + j * 8, 16);
        CP_COMMIT();
    };

    fill(0, 0); fill(1, 64); fill(2, 128);

    float acc[4][8][4] = {};
    GEMM_FRAGS
    GEMM_MAINLOOP(HID / 64)
    __syncthreads();

    float* st = (float*)smem;   // [128][EPI_STR]
    GEMM_EPI_STAGE(st)
    __syncthreads();

    __half* Out = z ? g_eo : g_shared;
    #pragma unroll
    for (int i = 0; i < 16; i++) {
        int f = tid + i * 256;
        int r = f >> 5, ch = f & 31;            // 32 chunks of 8 halfs = 256 cols
        if (r < nrows) {
            float sc = z ? g_permw[rowStart + r] : 1.f;
            const float* s0 = st + r * EPI_STR + ch * 8;
            __half2 h0 = __floats2half2_rn(sc * s0[0], sc * s0[1]);
            __half2 h1 = __floats2half2_rn(sc * s0[2], sc * s0[3]);
            __half2 h2 = __floats2half2_rn(sc * s0[4], sc * s0[5]);
            __half2 h3 = __floats2half2_rn(sc * s0[6], sc * s0[7]);
            uint4 u;
            u.x = *(uint32_t*)&h0; u.y = *(uint32_t*)&h1;
            u.z = *(uint32_t*)&h2; u.w = *(uint32_t*)&h3;
            *(uint4*)(Out + (size_t)(rowStart + r) * LLM + colBase + ch * 8) = u;
        }
    }
}

// ---------------- kernel 7: combine + LN_post (fp16 inputs) ------------------
__global__ __launch_bounds__(256) void ln_post_kernel(
    const float* __restrict__ lng, const float* __restrict__ lnb,
    float* __restrict__ out)
{
    int t = blockIdx.x;
    int tid = threadIdx.x;
    int p0 = g_pos[2 * t + 0], p1 = g_pos[2 * t + 1];
    const __half2* sh = (const __half2*)(g_shared + (size_t)t * LLM);
    const __half2* e0 = (const __half2*)(g_eo + (size_t)p0 * LLM);
    const __half2* e1 = (const __half2*)(g_eo + (size_t)p1 * LLM);
    float2 v[4];
    float sum = 0.f, sq = 0.f;
    #pragma unroll
    for (int i = 0; i < 4; i++) {
        int j = tid + i * 256;          // half2 index, j < 1024
        float2 a = __half22float2(sh[j]);
        float2 b = __half22float2(e0[j]);
        float2 c = __half22float2(e1[j]);
        float2 val = make_float2(a.x + b.x + c.x, a.y + b.y + c.y);
        v[i] = val;
        sum += val.x + val.y;
        sq += val.x * val.x + val.y * val.y;
    }
    blockReduce2(sum, sq);
    float m = sum * (1.f / LLM);
    float var = sq * (1.f / LLM) - m * m;
    float rinv = rsqrtf(var + 1e-6f);
    float* orow = out + (size_t)t * LLM;
    #pragma unroll
    for (int i = 0; i < 4; i++) {
        int j = tid + i * 256;
        float2 gv = ((const float2*)lng)[j];
        float2 bv = ((const float2*)lnb)[j];
        float2 o;
        o.x = (v[i].x - m) * rinv * gv.x + bv.x;
        o.y = (v[i].y - m) * rinv * gv.y + bv.y;
        *(float2*)(orow + 2 * j) = o;
    }
}

// ---------------- launcher ----------------------------------------------------
extern "C" void kernel_launch(void* const* d_in, const int* in_sizes, int n_in,
                              void* d_out, int out_size)
{
    const float* x           = (const float*)d_in[0];
    const float* ln_pre_g    = (const float*)d_in[1];
    const float* ln_pre_b    = (const float*)d_in[2];
    const float* router_w    = (const float*)d_in[3];
    const float* router_b    = (const float*)d_in[4];
    const float* shared_w12  = (const float*)d_in[5];
    const float* shared_w3   = (const float*)d_in[6];
    const float* experts_w12 = (const float*)d_in[7];
    const float* experts_w3  = (const float*)d_in[8];
    const float* ln_post_g   = (const float*)d_in[9];
    const float* ln_post_b   = (const float*)d_in[10];
    float* out = (float*)d_out;

    const int RW_SMEM = NE * D_IN * 4;  // 80 KB
    cudaFuncSetAttribute(gemm12_mma, cudaFuncAttributeMaxDynamicSharedMemorySize, SMEM_DYN);
    cudaFuncSetAttribute(gemm3_mma,  cudaFuncAttributeMaxDynamicSharedMemorySize, SMEM_DYN);
    cudaFuncSetAttribute(router_kernel, cudaFuncAttributeMaxDynamicSharedMemorySize, RW_SMEM);

    cvt_weights<<<4096, 256>>>((const float4*)shared_w12, (const float4*)shared_w3,
                               (const float4*)experts_w12, (const float4*)experts_w3);
    ln_pre_kernel<<<T_TOK, 256>>>(x, ln_pre_g, ln_pre_b);
    router_kernel<<<(T_TOK + 127) / 128, 256, RW_SMEM>>>(router_w, router_b);
    scan_kernel<<<1, 32>>>();
    build_kernel<<<(T_TOK + 255) / 256, 256>>>();

    const int MT = (T_TOK + 127) / 128;   // 94 (also covers worst-case expert)
    gemm12_mma<<<dim3(HID / 128, MT, NE + 1), 256, SMEM_DYN>>>();
    gemm3_mma <<<dim3(LLM / 256, MT, NE + 1), 256, SMEM_DYN>>>();

    ln_post_kernel<<<T_TOK, 256>>>(ln_post_g, ln_post_b, out);
}

// round 9
// speedup vs baseline: 4.1750x; 1.0079x over previous
#include <cuda_runtime.h>
#include <cuda_fp16.h>
#include <math.h>
#include <stdint.h>

// ---------------- problem constants ----------------------------------------
#define T_TOK 12000          // B*S/K tokens
#define D_IN  2560           // ENC*K
#define HID   512
#define LLM   2048
#define NE    8
#define NTOP  2
#define TWO   (T_TOK*NTOP)   // 24000 (token,slot) pairs

// ---------------- static device scratch ------------------------------------
__device__ __half g_nx[(size_t)T_TOK * D_IN];       // LN'd input (fp16, GEMM)
__device__ float  g_nx32[(size_t)T_TOK * D_IN];     // LN'd input (fp32, router)
__device__ __half g_act[(size_t)T_TOK * HID];       // shared swiglu (fp16)
__device__ __half g_shared[(size_t)T_TOK * LLM];    // shared out (fp16)
__device__ __half g_eact[(size_t)TWO * HID];        // expert swiglu (fp16)
__device__ __half g_eo[(size_t)TWO * LLM];          // expert out (fp16)
__device__ __half g_w12s[(size_t)2 * HID * D_IN];   // fp16 weights
__device__ __half g_w3s[(size_t)LLM * HID];
__device__ __half g_w12e[(size_t)NE * 2 * HID * D_IN];
__device__ __half g_w3e[(size_t)NE * LLM * HID];
__device__ int   g_idx[TWO];
__device__ float g_w[TWO];
__device__ int   g_perm[TWO];
__device__ float g_permw[TWO];
__device__ int   g_pos[TWO];
__device__ int   g_cnt[NE];
__device__ int   g_off[NE + 1];
__device__ int   g_cur[NE];

// ---------------- PTX helpers (sm_80-era; safe for plain sm_100) -----------
__device__ __forceinline__ uint32_t smem_u32(const void* p) {
    uint32_t a;
    asm("{ .reg .u64 t; cvta.to.shared.u64 t, %1; cvt.u32.u64 %0, t; }" : "=r"(a) : "l"(p));
    return a;
}
__device__ __forceinline__ void cpa16(uint32_t dst, const void* src, uint32_t srcsz) {
    asm volatile("cp.async.cg.shared.global [%0], [%1], 16, %2;"
                 :: "r"(dst), "l"(src), "r"(srcsz) : "memory");
}
#define CP_COMMIT() asm volatile("cp.async.commit_group;" ::: "memory")
#define CP_WAIT3()  asm volatile("cp.async.wait_group 3;" ::: "memory")

__device__ __forceinline__ void ldsm4(uint32_t& r0, uint32_t& r1, uint32_t& r2, uint32_t& r3,
                                      uint32_t addr) {
    asm volatile("ldmatrix.sync.aligned.m8n8.x4.shared.b16 {%0,%1,%2,%3}, [%4];"
                 : "=r"(r0), "=r"(r1), "=r"(r2), "=r"(r3) : "r"(addr));
}
__device__ __forceinline__ void mma_f16(float* c,
                                        uint32_t a0, uint32_t a1, uint32_t a2, uint32_t a3,
                                        uint32_t b0, uint32_t b1) {
    asm volatile(
        "mma.sync.aligned.m16n8k16.row.col.f32.f16.f16.f32 "
        "{%0,%1,%2,%3}, {%4,%5,%6,%7}, {%8,%9}, {%0,%1,%2,%3};"
        : "+f"(c[0]), "+f"(c[1]), "+f"(c[2]), "+f"(c[3])
        : "r"(a0), "r"(a1), "r"(a2), "r"(a3), "r"(b0), "r"(b1));
}

// ---------------- smem geometry ---------------------------------------------
#define ASTRB    144
#define A_BYTES  (128 * ASTRB)            // 18432
#define B_BYTES  (256 * ASTRB)            // 36864
#define STAGE_B  (A_BYTES + B_BYTES)      // 55296
#define SMEM_DYN (4 * STAGE_B)            // 221184, 4-stage pipeline
#define EPI_STR  264                      // fp32 epilogue stage stride

// ---------------- misc helpers ----------------------------------------------
__device__ __forceinline__ void blockReduce2(float& sum, float& sq) {
    __shared__ float ss[8], sv[8];
    #pragma unroll
    for (int o = 16; o > 0; o >>= 1) {
        sum += __shfl_down_sync(0xFFFFFFFFu, sum, o);
        sq  += __shfl_down_sync(0xFFFFFFFFu, sq,  o);
    }
    int w = threadIdx.x >> 5, l = threadIdx.x & 31;
    if (l == 0) { ss[w] = sum; sv[w] = sq; }
    __syncthreads();
    if (w == 0) {
        sum = (l < 8) ? ss[l] : 0.f;
        sq  = (l < 8) ? sv[l] : 0.f;
        #pragma unroll
        for (int o = 4; o > 0; o >>= 1) {
            sum += __shfl_down_sync(0xFFFFFFFFu, sum, o);
            sq  += __shfl_down_sync(0xFFFFFFFFu, sq,  o);
        }
        if (l == 0) { ss[0] = sum; sv[0] = sq; }
    }
    __syncthreads();
    sum = ss[0]; sq = sv[0];
}

// ---------------- kernel 0: convert weights to fp16 (+ zero counters) -------
__global__ __launch_bounds__(256) void cvt_weights(
    const float4* __restrict__ s12, const float4* __restrict__ s3,
    const float4* __restrict__ e12, const float4* __restrict__ e3)
{
    if (blockIdx.x == 0 && threadIdx.x < NE) {
        g_cnt[threadIdx.x] = 0;
        g_cur[threadIdx.x] = 0;
    }
    const int N1 = 2 * HID * D_IN / 4;
    const int N2 = LLM * HID / 4;
    const int N3 = NE * 2 * HID * D_IN / 4;
    const int N4 = NE * LLM * HID / 4;
    const int total = N1 + N2 + N3 + N4;
    for (int i = blockIdx.x * blockDim.x + threadIdx.x; i < total;
         i += gridDim.x * blockDim.x) {
        float4 v; __half2* dst;
        int j = i;
        if (j < N1)              { v = s12[j]; dst = (__half2*)g_w12s + 2 * j; }
        else if ((j -= N1) < N2) { v = s3[j];  dst = (__half2*)g_w3s  + 2 * j; }
        else if ((j -= N2) < N3) { v = e12[j]; dst = (__half2*)g_w12e + 2 * j; }
        else { j -= N3;           v = e3[j];  dst = (__half2*)g_w3e  + 2 * j; }
        dst[0] = __floats2half2_rn(v.x, v.y);
        dst[1] = __floats2half2_rn(v.z, v.w);
    }
}

// ---------------- kernel 1: LN_pre (fp16 for GEMM + fp32 for router) --------
__global__ __launch_bounds__(256) void ln_pre_kernel(
    const float* __restrict__ x,
    const float* __restrict__ lng, const float* __restrict__ lnb)
{
    int t = blockIdx.x;
    const float* xr = x + (size_t)t * D_IN;
    int tid = threadIdx.x;
    float v[10];
    float sum = 0.f, sq = 0.f;
    #pragma unroll
    for (int i = 0; i < 10; i++) {
        v[i] = xr[tid + i * 256];
        sum += v[i]; sq += v[i] * v[i];
    }
    blockReduce2(sum, sq);
    float m = sum * (1.f / D_IN);
    float var = sq * (1.f / D_IN) - m * m;
    float rinv = rsqrtf(var + 1e-6f);
    __half* nxr = g_nx + (size_t)t * D_IN;
    float* nxr32 = g_nx32 + (size_t)t * D_IN;
    #pragma unroll
    for (int i = 0; i < 10; i++) {
        int j = tid + i * 256;
        float nv = (v[i] - m) * rinv * lng[j] + lnb[j];
        nxr32[j] = nv;                       // fp32: router fidelity
        nxr[j] = __float2half_rn(nv);        // fp16: GEMM operand
    }
}

// ---------------- kernel 2: tiled router (64 tokens/block, 188 blocks) ------
__global__ __launch_bounds__(256) void router_kernel(
    const float* __restrict__ rw, const float* __restrict__ rb)
{
    extern __shared__ __align__(16) char smem[];
    float* s_rw = (float*)smem;                 // [NE][D_IN] fp32 = 80KB
    __shared__ int s_cnt[NE];
    int tid = threadIdx.x;
    if (tid < NE) s_cnt[tid] = 0;
    for (int i = tid; i < NE * D_IN / 4; i += 256)
        ((float4*)s_rw)[i] = ((const float4*)rw)[i];
    __syncthreads();

    int wid = tid >> 5, lane = tid & 31;
    for (int it = 0; it < 8; it++) {
        int t = blockIdx.x * 64 + wid * 8 + it;
        if (t >= T_TOK) break;
        const float2* row = (const float2*)(g_nx32 + (size_t)t * D_IN);
        float2 h[40];
        #pragma unroll
        for (int j = 0; j < 40; j++) h[j] = row[lane + j * 32];
        float lg[NE];
        #pragma unroll
        for (int e = 0; e < NE; e++) {
            const float2* w2 = (const float2*)(s_rw + e * D_IN);
            float acc = 0.f;
            #pragma unroll
            for (int j = 0; j < 40; j++) {
                float2 wv = w2[lane + j * 32];
                acc = fmaf(h[j].x, wv.x, acc);
                acc = fmaf(h[j].y, wv.y, acc);
            }
            #pragma unroll
            for (int o = 16; o > 0; o >>= 1)
                acc += __shfl_down_sync(0xFFFFFFFFu, acc, o);
            lg[e] = acc;
        }
        if (lane == 0) {
            float p[NE];
            float mx = lg[0] + rb[0];
            #pragma unroll
            for (int e = 0; e < NE; e++) { p[e] = lg[e] + rb[e]; mx = fmaxf(mx, p[e]); }
            float se = 0.f;
            #pragma unroll
            for (int e = 0; e < NE; e++) { p[e] = __expf(p[e] - mx); se += p[e]; }
            float rse = 1.f / se;
            #pragma unroll
            for (int e = 0; e < NE; e++) p[e] *= rse;
            int i0 = 0;
            #pragma unroll
            for (int e = 1; e < NE; e++) if (p[e] > p[i0]) i0 = e;
            int i1 = (i0 == 0) ? 1 : 0;
            #pragma unroll
            for (int e = 0; e < NE; e++) if (e != i0 && p[e] > p[i1]) i1 = e;
            float s2 = p[i0] + p[i1] + 1e-20f;
            g_idx[2 * t + 0] = i0; g_w[2 * t + 0] = p[i0] / s2;
            g_idx[2 * t + 1] = i1; g_w[2 * t + 1] = p[i1] / s2;
            atomicAdd(&s_cnt[i0], 1);
            atomicAdd(&s_cnt[i1], 1);
        }
    }
    __syncthreads();
    if (tid < NE && s_cnt[tid]) atomicAdd(&g_cnt[tid], s_cnt[tid]);
}

// ---------------- kernel 3/4: scan + permutation (aggregated atomics) -------
__global__ void scan_kernel() {
    if (threadIdx.x == 0) {
        int o = 0;
        for (int e = 0; e < NE; e++) { g_off[e] = o; o += g_cnt[e]; }
        g_off[NE] = o;
    }
}
__global__ __launch_bounds__(256) void build_kernel() {
    __shared__ int s_cur[NE], s_base[NE];
    int tid = threadIdx.x;
    if (tid < NE) s_cur[tid] = 0;
    __syncthreads();
    int t = blockIdx.x * 256 + tid;
    int e2[2], lp[2];
    if (t < T_TOK) {
        #pragma unroll
        for (int k = 0; k < NTOP; k++) {
            e2[k] = g_idx[2 * t + k];
            lp[k] = atomicAdd(&s_cur[e2[k]], 1);
        }
    }
    __syncthreads();
    if (tid < NE) s_base[tid] = s_cur[tid] ? atomicAdd(&g_cur[tid], s_cur[tid]) : 0;
    __syncthreads();
    if (t < T_TOK) {
        #pragma unroll
        for (int k = 0; k < NTOP; k++) {
            int p = g_off[e2[k]] + s_base[e2[k]] + lp[k];
            g_perm[p]  = t;
            g_permw[p] = g_w[2 * t + k];
            g_pos[2 * t + k] = p;
        }
    }
}

// ============================================================================
// fp16 mma core: CTA 128x256, BK=64, 256 threads, 8 warps (2x4), warp 64x64
// Register double-buffered fragment pipeline inside each k-tile.
// ============================================================================
#define GEMM_FRAGS                                                            \
    const int lane = threadIdx.x & 31, wid = threadIdx.x >> 5;                \
    const int wm = (wid >> 2) * 64, wn = (wid & 3) * 64;                      \
    const int l16 = lane & 15, lh = lane >> 4;                                \
    const int bg = lane >> 3;                                                 \
    const int b_row = ((bg & 1) << 3) + (lane & 7), b_ch = bg >> 1;

#define LOAD_FRAGS(A, B, abase, bbase, step)                                  \
    _Pragma("unroll")                                                         \
    for (int mf = 0; mf < 4; mf++)                                            \
        ldsm4((A)[mf][0], (A)[mf][1], (A)[mf][2], (A)[mf][3],                 \
              (abase) + (wm + mf * 16 + l16) * ASTRB + ((step) * 2 + lh) * 16); \
    _Pragma("unroll")                                                         \
    for (int nb = 0; nb < 4; nb++)                                            \
        ldsm4((B)[nb][0], (B)[nb][1], (B)[nb][2], (B)[nb][3],                 \
              (bbase) + (wn + nb * 16 + b_row) * ASTRB + ((step) * 2 + b_ch) * 16);

#define MMA_FRAGS(A, B)                                                       \
    _Pragma("unroll")                                                         \
    for (int mf = 0; mf < 4; mf++)                                            \
        _Pragma("unroll")                                                     \
        for (int nb = 0; nb < 4; nb++) {                                      \
            mma_f16(acc[mf][2 * nb],     (A)[mf][0], (A)[mf][1], (A)[mf][2], (A)[mf][3], (B)[nb][0], (B)[nb][2]); \
            mma_f16(acc[mf][2 * nb + 1], (A)[mf][0], (A)[mf][1], (A)[mf][2], (A)[mf][3], (B)[nb][1], (B)[nb][3]); \
        }

#define GEMM_MAINLOOP(NK)                                                     \
    uint32_t af[2][4][4], bf[2][4][4];                                        \
    for (int kt = 0; kt < (NK); kt++) {                                       \
        CP_WAIT3();                                                           \
        __syncthreads();                                                      \
        uint32_t abase = sbase + (kt & 3) * STAGE_B;                          \
        uint32_t bbase = abase + A_BYTES;                                     \
        LOAD_FRAGS(af[0], bf[0], abase, bbase, 0)                             \
        if (kt + 3 < (NK)) fill((kt + 3) & 3, (kt + 3) * 64);                 \
        else CP_COMMIT();                                                     \
        _Pragma("unroll")                                                     \
        for (int step = 0; step < 4; step++) {                                \
            if (step < 3) { LOAD_FRAGS(af[(step + 1) & 1], bf[(step + 1) & 1], abase, bbase, step + 1) } \
            MMA_FRAGS(af[step & 1], bf[step & 1])                             \
        }                                                                     \
    }

#define GEMM_EPI_STAGE(st)                                                    \
    {                                                                         \
        const int cg = lane >> 2, ct = lane & 3;                              \
        _Pragma("unroll")                                                     \
        for (int mf = 0; mf < 4; mf++) {                                      \
            int row = wm + mf * 16 + cg;                                      \
            _Pragma("unroll")                                                 \
            for (int nf = 0; nf < 8; nf++) {                                  \
                int col = wn + nf * 8 + ct * 2;                               \
                *(float2*)((st) + row * EPI_STR + col)       = make_float2(acc[mf][nf][0], acc[mf][nf][1]); \
                *(float2*)((st) + (row + 8) * EPI_STR + col) = make_float2(acc[mf][nf][2], acc[mf][nf][3]); \
            }                                                                 \
        }                                                                     \
    }

// ============================================================================
// kernel 5: GEMM w12 + fused SwiGLU, merged shared(z=0)/expert(z=1..8)
// ============================================================================
__global__ __launch_bounds__(256, 1) void gemm12_mma()
{
    const int z = blockIdx.z;
    int rowStart, nrows;
    const __half* W;
    if (z == 0) {
        rowStart = blockIdx.y * 128;
        if (rowStart >= T_TOK) return;
        nrows = min(128, T_TOK - rowStart);
        W = g_w12s;
    } else {
        int e = z - 1;
        int re = g_off[e + 1];
        rowStart = g_off[e] + blockIdx.y * 128;
        if (rowStart >= re) return;
        nrows = min(128, re - rowStart);
        W = g_w12e + (size_t)e * (2 * HID) * D_IN;
    }
    const int colBase = blockIdx.x * 128;   // act column tile

    extern __shared__ __align__(16) char smem[];
    __shared__ int s_perm[128];
    const uint32_t sbase = smem_u32(smem);
    const int tid = threadIdx.x;

    if (z && tid < 128)
        s_perm[tid] = (tid < nrows) ? g_perm[rowStart + tid] : 0;
    __syncthreads();

    const int arow = tid >> 1;
    const uint32_t avalid = (arow < nrows) ? 16 : 0;
    const __half* srcA = (z ? (g_nx + (size_t)s_perm[arow] * D_IN)
                            : (g_nx + (size_t)(rowStart + min(arow, nrows - 1)) * D_IN))
                         + (tid & 1) * 32;
    const int wrow = (tid < 128) ? (colBase + tid) : (HID + colBase + (tid - 128));
    const __half* srcB = W + (size_t)wrow * D_IN;
    const uint32_t adst0 = sbase + arow * ASTRB + (tid & 1) * 64;
    const uint32_t bdst0 = sbase + A_BYTES + tid * ASTRB;

    auto fill = [&](int s, int k0) {
        uint32_t ad = adst0 + s * STAGE_B;
        #pragma unroll
        for (int j = 0; j < 4; j++) cpa16(ad + j * 16, srcA + k0 + j * 8, avalid);
        uint32_t bd = bdst0 + s * STAGE_B;
        #pragma unroll
        for (int j = 0; j < 8; j++) cpa16(bd + j * 16, srcB + k0 + j * 8, 16);
        CP_COMMIT();
    };

    fill(0, 0); fill(1, 64); fill(2, 128);

    float acc[4][8][4] = {};
    GEMM_FRAGS
    GEMM_MAINLOOP(D_IN / 64)
    __syncthreads();

    float* st = (float*)smem;   // [128][EPI_STR]
    GEMM_EPI_STAGE(st)
    __syncthreads();

    __half* Out = z ? g_eact : g_act;
    #pragma unroll
    for (int i = 0; i < 16; i++) {
        int f = tid + i * 256;
        int r = f >> 5, c4 = f & 31;            // 32 x 4-half chunks = 128 cols
        if (r < nrows) {
            float4 gg = *(float4*)(st + r * EPI_STR + c4 * 4);
            float4 vv = *(float4*)(st + r * EPI_STR + 128 + c4 * 4);
            __half2 h0 = __floats2half2_rn(gg.x / (1.f + __expf(-gg.x)) * vv.x,
                                           gg.y / (1.f + __expf(-gg.y)) * vv.y);
            __half2 h1 = __floats2half2_rn(gg.z / (1.f + __expf(-gg.z)) * vv.z,
                                           gg.w / (1.f + __expf(-gg.w)) * vv.w);
            uint32_t u0 = *(uint32_t*)&h0, u1 = *(uint32_t*)&h1;
            *(uint2*)(Out + (size_t)(rowStart + r) * HID + colBase + c4 * 4) =
                make_uint2(u0, u1);
        }
    }
}

// ============================================================================
// kernel 6: GEMM w3 (+ fused routing weight), merged z, K=512, fp16 output
// ============================================================================
__global__ __launch_bounds__(256, 1) void gemm3_mma()
{
    const int z = blockIdx.z;
    int rowStart, nrows;
    const __half* W;
    if (z == 0) {
        rowStart = blockIdx.y * 128;
        if (rowStart >= T_TOK) return;
        nrows = min(128, T_TOK - rowStart);
        W = g_w3s;
    } else {
        int e = z - 1;
        int re = g_off[e + 1];
        rowStart = g_off[e] + blockIdx.y * 128;
        if (rowStart >= re) return;
        nrows = min(128, re - rowStart);
        W = g_w3e + (size_t)e * LLM * HID;
    }
    const int colBase = blockIdx.x * 256;
    const __half* Act = z ? g_eact : g_act;

    extern __shared__ __align__(16) char smem[];
    const uint32_t sbase = smem_u32(smem);
    const int tid = threadIdx.x;

    const int arow = tid >> 1;
    const uint32_t avalid = (arow < nrows) ? 16 : 0;
    const __half* srcA = Act + (size_t)(rowStart + min(arow, nrows - 1)) * HID + (tid & 1) * 32;
    const __half* srcB = W + (size_t)(colBase + tid) * HID;
    const uint32_t adst0 = sbase + arow * ASTRB + (tid & 1) * 64;
    const uint32_t bdst0 = sbase + A_BYTES + tid * ASTRB;

    auto fill = [&](int s, int k0) {
        uint32_t ad = adst0 + s * STAGE_B;
        #pragma unroll
        for (int j = 0; j < 4; j++) cpa16(ad + j * 16, srcA + k0 + j * 8, avalid);
        uint32_t bd = bdst0 + s * STAGE_B;
        #pragma unroll
        for (int j = 0; j < 8; j++) cpa16(bd + j * 16, srcB + k0 + j * 8, 16);
        CP_COMMIT();
    };

    fill(0, 0); fill(1, 64); fill(2, 128);

    float acc[4][8][4] = {};
    GEMM_FRAGS
    GEMM_MAINLOOP(HID / 64)
    __syncthreads();

    float* st = (float*)smem;   // [128][EPI_STR]
    GEMM_EPI_STAGE(st)
    __syncthreads();

    __half* Out = z ? g_eo : g_shared;
    #pragma unroll
    for (int i = 0; i < 16; i++) {
        int f = tid + i * 256;
        int r = f >> 5, ch = f & 31;            // 32 chunks of 8 halfs = 256 cols
        if (r < nrows) {
            float sc = z ? g_permw[rowStart + r] : 1.f;
            const float* s0 = st + r * EPI_STR + ch * 8;
            __half2 h0 = __floats2half2_rn(sc * s0[0], sc * s0[1]);
            __half2 h1 = __floats2half2_rn(sc * s0[2], sc * s0[3]);
            __half2 h2 = __floats2half2_rn(sc * s0[4], sc * s0[5]);
            __half2 h3 = __floats2half2_rn(sc * s0[6], sc * s0[7]);
            uint4 u;
            u.x = *(uint32_t*)&h0; u.y = *(uint32_t*)&h1;
            u.z = *(uint32_t*)&h2; u.w = *(uint32_t*)&h3;
            *(uint4*)(Out + (size_t)(rowStart + r) * LLM + colBase + ch * 8) = u;
        }
    }
}

// ---------------- kernel 7: combine + LN_post (fp16 inputs) ------------------
__global__ __launch_bounds__(256) void ln_post_kernel(
    const float* __restrict__ lng, const float* __restrict__ lnb,
    float* __restrict__ out)
{
    int t = blockIdx.x;
    int tid = threadIdx.x;
    int p0 = g_pos[2 * t + 0], p1 = g_pos[2 * t + 1];
    const __half2* sh = (const __half2*)(g_shared + (size_t)t * LLM);
    const __half2* e0 = (const __half2*)(g_eo + (size_t)p0 * LLM);
    const __half2* e1 = (const __half2*)(g_eo + (size_t)p1 * LLM);
    float2 v[4];
    float sum = 0.f, sq = 0.f;
    #pragma unroll
    for (int i = 0; i < 4; i++) {
        int j = tid + i * 256;          // half2 index, j < 1024
        float2 a = __half22float2(sh[j]);
        float2 b = __half22float2(e0[j]);
        float2 c = __half22float2(e1[j]);
        float2 val = make_float2(a.x + b.x + c.x, a.y + b.y + c.y);
        v[i] = val;
        sum += val.x + val.y;
        sq += val.x * val.x + val.y * val.y;
    }
    blockReduce2(sum, sq);
    float m = sum * (1.f / LLM);
    float var = sq * (1.f / LLM) - m * m;
    float rinv = rsqrtf(var + 1e-6f);
    float* orow = out + (size_t)t * LLM;
    #pragma unroll
    for (int i = 0; i < 4; i++) {
        int j = tid + i * 256;
        float2 gv = ((const float2*)lng)[j];
        float2 bv = ((const float2*)lnb)[j];
        float2 o;
        o.x = (v[i].x - m) * rinv * gv.x + bv.x;
        o.y = (v[i].y - m) * rinv * gv.y + bv.y;
        *(float2*)(orow + 2 * j) = o;
    }
}

// ---------------- launcher ----------------------------------------------------
extern "C" void kernel_launch(void* const* d_in, const int* in_sizes, int n_in,
                              void* d_out, int out_size)
{
    const float* x           = (const float*)d_in[0];
    const float* ln_pre_g    = (const float*)d_in[1];
    const float* ln_pre_b    = (const float*)d_in[2];
    const float* router_w    = (const float*)d_in[3];
    const float* router_b    = (const float*)d_in[4];
    const float* shared_w12  = (const float*)d_in[5];
    const float* shared_w3   = (const float*)d_in[6];
    const float* experts_w12 = (const float*)d_in[7];
    const float* experts_w3  = (const float*)d_in[8];
    const float* ln_post_g   = (const float*)d_in[9];
    const float* ln_post_b   = (const float*)d_in[10];
    float* out = (float*)d_out;

    const int RW_SMEM = NE * D_IN * 4;  // 80 KB
    cudaFuncSetAttribute(gemm12_mma, cudaFuncAttributeMaxDynamicSharedMemorySize, SMEM_DYN);
    cudaFuncSetAttribute(gemm3_mma,  cudaFuncAttributeMaxDynamicSharedMemorySize, SMEM_DYN);
    cudaFuncSetAttribute(router_kernel, cudaFuncAttributeMaxDynamicSharedMemorySize, RW_SMEM);

    cvt_weights<<<4096, 256>>>((const float4*)shared_w12, (const float4*)shared_w3,
                               (const float4*)experts_w12, (const float4*)experts_w3);
    ln_pre_kernel<<<T_TOK, 256>>>(x, ln_pre_g, ln_pre_b);
    router_kernel<<<(T_TOK + 63) / 64, 256, RW_SMEM>>>(router_w, router_b);
    scan_kernel<<<1, 32>>>();
    build_kernel<<<(T_TOK + 255) / 256, 256>>>();

    const int MT = (T_TOK + 127) / 128;   // 94 (also covers worst-case expert)
    gemm12_mma<<<dim3(HID / 128, MT, NE + 1), 256, SMEM_DYN>>>();
    gemm3_mma <<<dim3(LLM / 256, MT, NE + 1), 256, SMEM_DYN>>>();

    ln_post_kernel<<<T_TOK, 256>>>(ln_post_g, ln_post_b, out);
}

// round 10
// speedup vs baseline: 4.8035x; 1.1505x over previous
#include <cuda_runtime.h>
#include <cuda_fp16.h>
#include <math.h>
#include <stdint.h>

// ---------------- problem constants ----------------------------------------
#define T_TOK 12000          // B*S/K tokens
#define D_IN  2560           // ENC*K
#define HID   512
#define LLM   2048
#define NE    8
#define NTOP  2
#define TWO   (T_TOK*NTOP)   // 24000 (token,slot) pairs

// ---------------- static device scratch ------------------------------------
__device__ __half g_nx[(size_t)T_TOK * D_IN];       // LN'd input (fp16, GEMM)
__device__ float  g_nx32[(size_t)T_TOK * D_IN];     // LN'd input (fp32, router)
__device__ __half g_act[(size_t)T_TOK * HID];       // shared swiglu (fp16)
__device__ __half g_shared[(size_t)T_TOK * LLM];    // shared out (fp16)
__device__ __half g_eact[(size_t)TWO * HID];        // expert swiglu (fp16)
__device__ __half g_eo[(size_t)TWO * LLM];          // expert out (fp16)
__device__ __half g_w12s[(size_t)2 * HID * D_IN];   // fp16 weights
__device__ __half g_w3s[(size_t)LLM * HID];
__device__ __half g_w12e[(size_t)NE * 2 * HID * D_IN];
__device__ __half g_w3e[(size_t)NE * LLM * HID];
__device__ int   g_idx[TWO];
__device__ float g_w[TWO];
__device__ int   g_perm[TWO];
__device__ float g_permw[TWO];
__device__ int   g_pos[TWO];
__device__ int   g_cnt[NE];
__device__ int   g_off[NE + 1];
__device__ int   g_cur[NE];

// ---------------- PTX helpers (sm_80-era; safe for plain sm_100) -----------
__device__ __forceinline__ uint32_t smem_u32(const void* p) {
    uint32_t a;
    asm("{ .reg .u64 t; cvta.to.shared.u64 t, %1; cvt.u32.u64 %0, t; }" : "=r"(a) : "l"(p));
    return a;
}
__device__ __forceinline__ void cpa16(uint32_t dst, const void* src, uint32_t srcsz) {
    asm volatile("cp.async.cg.shared.global [%0], [%1], 16, %2;"
                 :: "r"(dst), "l"(src), "r"(srcsz) : "memory");
}
#define CP_COMMIT() asm volatile("cp.async.commit_group;" ::: "memory")
#define CP_WAIT3()  asm volatile("cp.async.wait_group 3;" ::: "memory")

__device__ __forceinline__ void ldsm4(uint32_t& r0, uint32_t& r1, uint32_t& r2, uint32_t& r3,
                                      uint32_t addr) {
    asm volatile("ldmatrix.sync.aligned.m8n8.x4.shared.b16 {%0,%1,%2,%3}, [%4];"
                 : "=r"(r0), "=r"(r1), "=r"(r2), "=r"(r3) : "r"(addr));
}
__device__ __forceinline__ void mma_f16(float* c,
                                        uint32_t a0, uint32_t a1, uint32_t a2, uint32_t a3,
                                        uint32_t b0, uint32_t b1) {
    asm volatile(
        "mma.sync.aligned.m16n8k16.row.col.f32.f16.f16.f32 "
        "{%0,%1,%2,%3}, {%4,%5,%6,%7}, {%8,%9}, {%0,%1,%2,%3};"
        : "+f"(c[0]), "+f"(c[1]), "+f"(c[2]), "+f"(c[3])
        : "r"(a0), "r"(a1), "r"(a2), "r"(a3), "r"(b0), "r"(b1));
}

// ---------------- smem geometry ---------------------------------------------
#define ASTRB    144
#define A_BYTES  (128 * ASTRB)            // 18432
#define B_BYTES  (256 * ASTRB)            // 36864
#define STAGE_B  (A_BYTES + B_BYTES)      // 55296
#define SMEM_DYN (4 * STAGE_B)            // 221184, 4-stage pipeline
#define EPI_STR  264                      // fp32 epilogue stage stride

// ---------------- misc helpers ----------------------------------------------
__device__ __forceinline__ void blockReduce2(float& sum, float& sq) {
    __shared__ float ss[8], sv[8];
    #pragma unroll
    for (int o = 16; o > 0; o >>= 1) {
        sum += __shfl_down_sync(0xFFFFFFFFu, sum, o);
        sq  += __shfl_down_sync(0xFFFFFFFFu, sq,  o);
    }
    int w = threadIdx.x >> 5, l = threadIdx.x & 31;
    if (l == 0) { ss[w] = sum; sv[w] = sq; }
    __syncthreads();
    if (w == 0) {
        sum = (l < 8) ? ss[l] : 0.f;
        sq  = (l < 8) ? sv[l] : 0.f;
        #pragma unroll
        for (int o = 4; o > 0; o >>= 1) {
            sum += __shfl_down_sync(0xFFFFFFFFu, sum, o);
            sq  += __shfl_down_sync(0xFFFFFFFFu, sq,  o);
        }
        if (l == 0) { ss[0] = sum; sv[0] = sq; }
    }
    __syncthreads();
    sum = ss[0]; sq = sv[0];
}

// ---------------- kernel 0: convert weights to fp16 (+ zero counters) -------
__global__ __launch_bounds__(256) void cvt_weights(
    const float4* __restrict__ s12, const float4* __restrict__ s3,
    const float4* __restrict__ e12, const float4* __restrict__ e3)
{
    if (blockIdx.x == 0 && threadIdx.x < NE) {
        g_cnt[threadIdx.x] = 0;
        g_cur[threadIdx.x] = 0;
    }
    const int N1 = 2 * HID * D_IN / 4;
    const int N2 = LLM * HID / 4;
    const int N3 = NE * 2 * HID * D_IN / 4;
    const int N4 = NE * LLM * HID / 4;
    const int total = N1 + N2 + N3 + N4;
    for (int i = blockIdx.x * blockDim.x + threadIdx.x; i < total;
         i += gridDim.x * blockDim.x) {
        float4 v; __half2* dst;
        int j = i;
        if (j < N1)              { v = s12[j]; dst = (__half2*)g_w12s + 2 * j; }
        else if ((j -= N1) < N2) { v = s3[j];  dst = (__half2*)g_w3s  + 2 * j; }
        else if ((j -= N2) < N3) { v = e12[j]; dst = (__half2*)g_w12e + 2 * j; }
        else { j -= N3;           v = e3[j];  dst = (__half2*)g_w3e  + 2 * j; }
        dst[0] = __floats2half2_rn(v.x, v.y);
        dst[1] = __floats2half2_rn(v.z, v.w);
    }
}

// ---------------- kernel 1: LN_pre (fp16 for GEMM + fp32 for router) --------
__global__ __launch_bounds__(256) void ln_pre_kernel(
    const float* __restrict__ x,
    const float* __restrict__ lng, const float* __restrict__ lnb)
{
    int t = blockIdx.x;
    const float* xr = x + (size_t)t * D_IN;
    int tid = threadIdx.x;
    float v[10];
    float sum = 0.f, sq = 0.f;
    #pragma unroll
    for (int i = 0; i < 10; i++) {
        v[i] = xr[tid + i * 256];
        sum += v[i]; sq += v[i] * v[i];
    }
    blockReduce2(sum, sq);
    float m = sum * (1.f / D_IN);
    float var = sq * (1.f / D_IN) - m * m;
    float rinv = rsqrtf(var + 1e-6f);
    __half* nxr = g_nx + (size_t)t * D_IN;
    float* nxr32 = g_nx32 + (size_t)t * D_IN;
    #pragma unroll
    for (int i = 0; i < 10; i++) {
        int j = tid + i * 256;
        float nv = (v[i] - m) * rinv * lng[j] + lnb[j];
        nxr32[j] = nv;                       // fp32: router fidelity
        nxr[j] = __float2half_rn(nv);        // fp16: GEMM operand
    }
}

// ---------------- kernel 2: tiled router (64 tokens/block, 188 blocks) ------
__global__ __launch_bounds__(256) void router_kernel(
    const float* __restrict__ rw, const float* __restrict__ rb)
{
    extern __shared__ __align__(16) char smem[];
    float* s_rw = (float*)smem;                 // [NE][D_IN] fp32 = 80KB
    __shared__ int s_cnt[NE];
    int tid = threadIdx.x;
    if (tid < NE) s_cnt[tid] = 0;
    for (int i = tid; i < NE * D_IN / 4; i += 256)
        ((float4*)s_rw)[i] = ((const float4*)rw)[i];
    __syncthreads();

    int wid = tid >> 5, lane = tid & 31;
    for (int it = 0; it < 8; it++) {
        int t = blockIdx.x * 64 + wid * 8 + it;
        if (t >= T_TOK) break;
        const float2* row = (const float2*)(g_nx32 + (size_t)t * D_IN);
        float2 h[40];
        #pragma unroll
        for (int j = 0; j < 40; j++) h[j] = row[lane + j * 32];
        float lg[NE];
        #pragma unroll
        for (int e = 0; e < NE; e++) {
            const float2* w2 = (const float2*)(s_rw + e * D_IN);
            float acc = 0.f;
            #pragma unroll
            for (int j = 0; j < 40; j++) {
                float2 wv = w2[lane + j * 32];
                acc = fmaf(h[j].x, wv.x, acc);
                acc = fmaf(h[j].y, wv.y, acc);
            }
            #pragma unroll
            for (int o = 16; o > 0; o >>= 1)
                acc += __shfl_down_sync(0xFFFFFFFFu, acc, o);
            lg[e] = acc;
        }
        if (lane == 0) {
            float p[NE];
            float mx = lg[0] + rb[0];
            #pragma unroll
            for (int e = 0; e < NE; e++) { p[e] = lg[e] + rb[e]; mx = fmaxf(mx, p[e]); }
            float se = 0.f;
            #pragma unroll
            for (int e = 0; e < NE; e++) { p[e] = __expf(p[e] - mx); se += p[e]; }
            float rse = 1.f / se;
            #pragma unroll
            for (int e = 0; e < NE; e++) p[e] *= rse;
            int i0 = 0;
            #pragma unroll
            for (int e = 1; e < NE; e++) if (p[e] > p[i0]) i0 = e;
            int i1 = (i0 == 0) ? 1 : 0;
            #pragma unroll
            for (int e = 0; e < NE; e++) if (e != i0 && p[e] > p[i1]) i1 = e;
            float s2 = p[i0] + p[i1] + 1e-20f;
            g_idx[2 * t + 0] = i0; g_w[2 * t + 0] = p[i0] / s2;
            g_idx[2 * t + 1] = i1; g_w[2 * t + 1] = p[i1] / s2;
            atomicAdd(&s_cnt[i0], 1);
            atomicAdd(&s_cnt[i1], 1);
        }
    }
    __syncthreads();
    if (tid < NE && s_cnt[tid]) atomicAdd(&g_cnt[tid], s_cnt[tid]);
}

// ---------------- kernel 3/4: scan + permutation (aggregated atomics) -------
__global__ void scan_kernel() {
    if (threadIdx.x == 0) {
        int o = 0;
        for (int e = 0; e < NE; e++) { g_off[e] = o; o += g_cnt[e]; }
        g_off[NE] = o;
    }
}
__global__ __launch_bounds__(256) void build_kernel() {
    __shared__ int s_cur[NE], s_base[NE];
    int tid = threadIdx.x;
    if (tid < NE) s_cur[tid] = 0;
    __syncthreads();
    int t = blockIdx.x * 256 + tid;
    int e2[2], lp[2];
    if (t < T_TOK) {
        #pragma unroll
        for (int k = 0; k < NTOP; k++) {
            e2[k] = g_idx[2 * t + k];
            lp[k] = atomicAdd(&s_cur[e2[k]], 1);
        }
    }
    __syncthreads();
    if (tid < NE) s_base[tid] = s_cur[tid] ? atomicAdd(&g_cur[tid], s_cur[tid]) : 0;
    __syncthreads();
    if (t < T_TOK) {
        #pragma unroll
        for (int k = 0; k < NTOP; k++) {
            int p = g_off[e2[k]] + s_base[e2[k]] + lp[k];
            g_perm[p]  = t;
            g_permw[p] = g_w[2 * t + k];
            g_pos[2 * t + k] = p;
        }
    }
}

// ============================================================================
// fp16 mma core: CTA 128x256, BK=64, 512 threads, 16 warps (4x4), warp 32x64
// 4 warps/SMSP for latency hiding; single-buffered fragments.
// ============================================================================
#define GEMM_FRAGS                                                            \
    const int lane = threadIdx.x & 31, wid = threadIdx.x >> 5;                \
    const int wm = (wid >> 2) * 32, wn = (wid & 3) * 64;                      \
    const int l16 = lane & 15, lh = lane >> 4;                                \
    const int bg = lane >> 3;                                                 \
    const int b_row = ((bg & 1) << 3) + (lane & 7), b_ch = bg >> 1;

#define LOAD_FRAGS(A, B, abase, bbase, step)                                  \
    _Pragma("unroll")                                                         \
    for (int mf = 0; mf < 2; mf++)                                            \
        ldsm4((A)[mf][0], (A)[mf][1], (A)[mf][2], (A)[mf][3],                 \
              (abase) + (wm + mf * 16 + l16) * ASTRB + ((step) * 2 + lh) * 16); \
    _Pragma("unroll")                                                         \
    for (int nb = 0; nb < 4; nb++)                                            \
        ldsm4((B)[nb][0], (B)[nb][1], (B)[nb][2], (B)[nb][3],                 \
              (bbase) + (wn + nb * 16 + b_row) * ASTRB + ((step) * 2 + b_ch) * 16);

#define MMA_FRAGS(A, B)                                                       \
    _Pragma("unroll")                                                         \
    for (int mf = 0; mf < 2; mf++)                                            \
        _Pragma("unroll")                                                     \
        for (int nb = 0; nb < 4; nb++) {                                      \
            mma_f16(acc[mf][2 * nb],     (A)[mf][0], (A)[mf][1], (A)[mf][2], (A)[mf][3], (B)[nb][0], (B)[nb][2]); \
            mma_f16(acc[mf][2 * nb + 1], (A)[mf][0], (A)[mf][1], (A)[mf][2], (A)[mf][3], (B)[nb][1], (B)[nb][3]); \
        }

#define GEMM_MAINLOOP(NK)                                                     \
    uint32_t af[2][4], bf[4][4];                                              \
    for (int kt = 0; kt < (NK); kt++) {                                       \
        CP_WAIT3();                                                           \
        __syncthreads();                                                      \
        uint32_t abase = sbase + (kt & 3) * STAGE_B;                          \
        uint32_t bbase = abase + A_BYTES;                                     \
        if (kt + 3 < (NK)) fill((kt + 3) & 3, (kt + 3) * 64);                 \
        else CP_COMMIT();                                                     \
        _Pragma("unroll")                                                     \
        for (int step = 0; step < 4; step++) {                                \
            LOAD_FRAGS(af, bf, abase, bbase, step)                            \
            MMA_FRAGS(af, bf)                                                 \
        }                                                                     \
    }

#define GEMM_EPI_STAGE(st)                                                    \
    {                                                                         \
        const int cg = lane >> 2, ct = lane & 3;                              \
        _Pragma("unroll")                                                     \
        for (int mf = 0; mf < 2; mf++) {                                      \
            int row = wm + mf * 16 + cg;                                      \
            _Pragma("unroll")                                                 \
            for (int nf = 0; nf < 8; nf++) {                                  \
                int col = wn + nf * 8 + ct * 2;                               \
                *(float2*)((st) + row * EPI_STR + col)       = make_float2(acc[mf][nf][0], acc[mf][nf][1]); \
                *(float2*)((st) + (row + 8) * EPI_STR + col) = make_float2(acc[mf][nf][2], acc[mf][nf][3]); \
            }                                                                 \
        }                                                                     \
    }

// ============================================================================
// kernel 5: GEMM w12 + fused SwiGLU, merged shared(z=0)/expert(z=1..8)
// ============================================================================
__global__ __launch_bounds__(512, 1) void gemm12_mma()
{
    const int z = blockIdx.z;
    int rowStart, nrows;
    const __half* W;
    if (z == 0) {
        rowStart = blockIdx.y * 128;
        if (rowStart >= T_TOK) return;
        nrows = min(128, T_TOK - rowStart);
        W = g_w12s;
    } else {
        int e = z - 1;
        int re = g_off[e + 1];
        rowStart = g_off[e] + blockIdx.y * 128;
        if (rowStart >= re) return;
        nrows = min(128, re - rowStart);
        W = g_w12e + (size_t)e * (2 * HID) * D_IN;
    }
    const int colBase = blockIdx.x * 128;   // act column tile

    extern __shared__ __align__(16) char smem[];
    __shared__ int s_perm[128];
    const uint32_t sbase = smem_u32(smem);
    const int tid = threadIdx.x;

    if (z && tid < 128)
        s_perm[tid] = (tid < nrows) ? g_perm[rowStart + tid] : 0;
    __syncthreads();

    // A: 512 threads cover 128 rows x 4 chunks of 32B
    const int arow = tid >> 2;
    const uint32_t avalid = (arow < nrows) ? 16 : 0;
    const __half* srcA = (z ? (g_nx + (size_t)s_perm[arow] * D_IN)
                            : (g_nx + (size_t)(rowStart + min(arow, nrows - 1)) * D_IN))
                         + (tid & 3) * 16;
    // B: 512 threads cover 256 rows x 2 chunks of 64B
    const int brow = tid >> 1;
    const int wrow = (brow < 128) ? (colBase + brow) : (HID + colBase + (brow - 128));
    const __half* srcB = W + (size_t)wrow * D_IN + (tid & 1) * 32;
    const uint32_t adst0 = sbase + arow * ASTRB + (tid & 3) * 32;
    const uint32_t bdst0 = sbase + A_BYTES + brow * ASTRB + (tid & 1) * 64;

    auto fill = [&](int s, int k0) {
        uint32_t ad = adst0 + s * STAGE_B;
        #pragma unroll
        for (int j = 0; j < 2; j++) cpa16(ad + j * 16, srcA + k0 + j * 8, avalid);
        uint32_t bd = bdst0 + s * STAGE_B;
        #pragma unroll
        for (int j = 0; j < 4; j++) cpa16(bd + j * 16, srcB + k0 + j * 8, 16);
        CP_COMMIT();
    };

    fill(0, 0); fill(1, 64); fill(2, 128);

    float acc[2][8][4] = {};
    GEMM_FRAGS
    GEMM_MAINLOOP(D_IN / 64)
    __syncthreads();

    float* st = (float*)smem;   // [128][EPI_STR]
    GEMM_EPI_STAGE(st)
    __syncthreads();

    __half* Out = z ? g_eact : g_act;
    #pragma unroll
    for (int i = 0; i < 8; i++) {
        int f = tid + i * 512;
        int r = f >> 5, c4 = f & 31;            // 32 x 4-half chunks = 128 cols
        if (r < nrows) {
            float4 gg = *(float4*)(st + r * EPI_STR + c4 * 4);
            float4 vv = *(float4*)(st + r * EPI_STR + 128 + c4 * 4);
            __half2 h0 = __floats2half2_rn(gg.x / (1.f + __expf(-gg.x)) * vv.x,
                                           gg.y / (1.f + __expf(-gg.y)) * vv.y);
            __half2 h1 = __floats2half2_rn(gg.z / (1.f + __expf(-gg.z)) * vv.z,
                                           gg.w / (1.f + __expf(-gg.w)) * vv.w);
            uint32_t u0 = *(uint32_t*)&h0, u1 = *(uint32_t*)&h1;
            *(uint2*)(Out + (size_t)(rowStart + r) * HID + colBase + c4 * 4) =
                make_uint2(u0, u1);
        }
    }
}

// ============================================================================
// kernel 6: GEMM w3 (+ fused routing weight), merged z, K=512, fp16 output
// ============================================================================
__global__ __launch_bounds__(512, 1) void gemm3_mma()
{
    const int z = blockIdx.z;
    int rowStart, nrows;
    const __half* W;
    if (z == 0) {
        rowStart = blockIdx.y * 128;
        if (rowStart >= T_TOK) return;
        nrows = min(128, T_TOK - rowStart);
        W = g_w3s;
    } else {
        int e = z - 1;
        int re = g_off[e + 1];
        rowStart = g_off[e] + blockIdx.y * 128;
        if (rowStart >= re) return;
        nrows = min(128, re - rowStart);
        W = g_w3e + (size_t)e * LLM * HID;
    }
    const int colBase = blockIdx.x * 256;
    const __half* Act = z ? g_eact : g_act;

    extern __shared__ __align__(16) char smem[];
    const uint32_t sbase = smem_u32(smem);
    const int tid = threadIdx.x;

    const int arow = tid >> 2;
    const uint32_t avalid = (arow < nrows) ? 16 : 0;
    const __half* srcA = Act + (size_t)(rowStart + min(arow, nrows - 1)) * HID + (tid & 3) * 16;
    const int brow = tid >> 1;
    const __half* srcB = W + (size_t)(colBase + brow) * HID + (tid & 1) * 32;
    const uint32_t adst0 = sbase + arow * ASTRB + (tid & 3) * 32;
    const uint32_t bdst0 = sbase + A_BYTES + brow * ASTRB + (tid & 1) * 64;

    auto fill = [&](int s, int k0) {
        uint32_t ad = adst0 + s * STAGE_B;
        #pragma unroll
        for (int j = 0; j < 2; j++) cpa16(ad + j * 16, srcA + k0 + j * 8, avalid);
        uint32_t bd = bdst0 + s * STAGE_B;
        #pragma unroll
        for (int j = 0; j < 4; j++) cpa16(bd + j * 16, srcB + k0 + j * 8, 16);
        CP_COMMIT();
    };

    fill(0, 0); fill(1, 64); fill(2, 128);

    float acc[2][8][4] = {};
    GEMM_FRAGS
    GEMM_MAINLOOP(HID / 64)
    __syncthreads();

    float* st = (float*)smem;   // [128][EPI_STR]
    GEMM_EPI_STAGE(st)
    __syncthreads();

    __half* Out = z ? g_eo : g_shared;
    #pragma unroll
    for (int i = 0; i < 8; i++) {
        int f = tid + i * 512;
        int r = f >> 5, ch = f & 31;            // 32 chunks of 8 halfs = 256 cols
        if (r < nrows) {
            float sc = z ? g_permw[rowStart + r] : 1.f;
            const float* s0 = st + r * EPI_STR + ch * 8;
            __half2 h0 = __floats2half2_rn(sc * s0[0], sc * s0[1]);
            __half2 h1 = __floats2half2_rn(sc * s0[2], sc * s0[3]);
            __half2 h2 = __floats2half2_rn(sc * s0[4], sc * s0[5]);
            __half2 h3 = __floats2half2_rn(sc * s0[6], sc * s0[7]);
            uint4 u;
            u.x = *(uint32_t*)&h0; u.y = *(uint32_t*)&h1;
            u.z = *(uint32_t*)&h2; u.w = *(uint32_t*)&h3;
            *(uint4*)(Out + (size_t)(rowStart + r) * LLM + colBase + ch * 8) = u;
        }
    }
}

// ---------------- kernel 7: combine + LN_post (fp16 inputs) ------------------
__global__ __launch_bounds__(256) void ln_post_kernel(
    const float* __restrict__ lng, const float* __restrict__ lnb,
    float* __restrict__ out)
{
    int t = blockIdx.x;
    int tid = threadIdx.x;
    int p0 = g_pos[2 * t + 0], p1 = g_pos[2 * t + 1];
    const __half2* sh = (const __half2*)(g_shared + (size_t)t * LLM);
    const __half2* e0 = (const __half2*)(g_eo + (size_t)p0 * LLM);
    const __half2* e1 = (const __half2*)(g_eo + (size_t)p1 * LLM);
    float2 v[4];
    float sum = 0.f, sq = 0.f;
    #pragma unroll
    for (int i = 0; i < 4; i++) {
        int j = tid + i * 256;          // half2 index, j < 1024
        float2 a = __half22float2(sh[j]);
        float2 b = __half22float2(e0[j]);
        float2 c = __half22float2(e1[j]);
        float2 val = make_float2(a.x + b.x + c.x, a.y + b.y + c.y);
        v[i] = val;
        sum += val.x + val.y;
        sq += val.x * val.x + val.y * val.y;
    }
    blockReduce2(sum, sq);
    float m = sum * (1.f / LLM);
    float var = sq * (1.f / LLM) - m * m;
    float rinv = rsqrtf(var + 1e-6f);
    float* orow = out + (size_t)t * LLM;
    #pragma unroll
    for (int i = 0; i < 4; i++) {
        int j = tid + i * 256;
        float2 gv = ((const float2*)lng)[j];
        float2 bv = ((const float2*)lnb)[j];
        float2 o;
        o.x = (v[i].x - m) * rinv * gv.x + bv.x;
        o.y = (v[i].y - m) * rinv * gv.y + bv.y;
        *(float2*)(orow + 2 * j) = o;
    }
}

// ---------------- launcher ----------------------------------------------------
extern "C" void kernel_launch(void* const* d_in, const int* in_sizes, int n_in,
                              void* d_out, int out_size)
{
    const float* x           = (const float*)d_in[0];
    const float* ln_pre_g    = (const float*)d_in[1];
    const float* ln_pre_b    = (const float*)d_in[2];
    const float* router_w    = (const float*)d_in[3];
    const float* router_b    = (const float*)d_in[4];
    const float* shared_w12  = (const float*)d_in[5];
    const float* shared_w3   = (const float*)d_in[6];
    const float* experts_w12 = (const float*)d_in[7];
    const float* experts_w3  = (const float*)d_in[8];
    const float* ln_post_g   = (const float*)d_in[9];
    const float* ln_post_b   = (const float*)d_in[10];
    float* out = (float*)d_out;

    const int RW_SMEM = NE * D_IN * 4;  // 80 KB
    cudaFuncSetAttribute(gemm12_mma, cudaFuncAttributeMaxDynamicSharedMemorySize, SMEM_DYN);
    cudaFuncSetAttribute(gemm3_mma,  cudaFuncAttributeMaxDynamicSharedMemorySize, SMEM_DYN);
    cudaFuncSetAttribute(router_kernel, cudaFuncAttributeMaxDynamicSharedMemorySize, RW_SMEM);

    cvt_weights<<<4096, 256>>>((const float4*)shared_w12, (const float4*)shared_w3,
                               (const float4*)experts_w12, (const float4*)experts_w3);
    ln_pre_kernel<<<T_TOK, 256>>>(x, ln_pre_g, ln_pre_b);
    router_kernel<<<(T_TOK + 63) / 64, 256, RW_SMEM>>>(router_w, router_b);
    scan_kernel<<<1, 32>>>();
    build_kernel<<<(T_TOK + 255) / 256, 256>>>();

    const int MT = (T_TOK + 127) / 128;   // 94 (also covers worst-case expert)
    gemm12_mma<<<dim3(HID / 128, MT, NE + 1), 512, SMEM_DYN>>>();
    gemm3_mma <<<dim3(LLM / 256, MT, NE + 1), 512, SMEM_DYN>>>();

    ln_post_kernel<<<T_TOK, 256>>>(ln_post_g, ln_post_b, out);
}

// round 11
// speedup vs baseline: 4.8071x; 1.0008x over previous
#include <cuda_runtime.h>
#include <cuda_fp16.h>
#include <math.h>
#include <stdint.h>

// ---------------- problem constants ----------------------------------------
#define T_TOK 12000          // B*S/K tokens
#define D_IN  2560           // ENC*K
#define HID   512
#define LLM   2048
#define NE    8
#define NTOP  2
#define TWO   (T_TOK*NTOP)   // 24000 (token,slot) pairs

// ---------------- static device scratch ------------------------------------
__device__ __half g_nx[(size_t)T_TOK * D_IN];       // LN'd input (fp16, GEMM)
__device__ __half g_act[(size_t)T_TOK * HID];       // shared swiglu (fp16)
__device__ __half g_shared[(size_t)T_TOK * LLM];    // shared out (fp16)
__device__ __half g_eact[(size_t)TWO * HID];        // expert swiglu (fp16)
__device__ __half g_eo[(size_t)TWO * LLM];          // expert out (fp16)
__device__ __half g_w12s[(size_t)2 * HID * D_IN];   // fp16 weights
__device__ __half g_w3s[(size_t)LLM * HID];
__device__ __half g_w12e[(size_t)NE * 2 * HID * D_IN];
__device__ __half g_w3e[(size_t)NE * LLM * HID];
__device__ int   g_idx[TWO];
__device__ float g_w[TWO];
__device__ int   g_perm[TWO];
__device__ float g_permw[TWO];
__device__ int   g_pos[TWO];
__device__ int   g_cnt[NE];
__device__ int   g_off[NE + 1];
__device__ int   g_cur[NE];

// ---------------- PTX helpers (sm_80-era; safe for plain sm_100) -----------
__device__ __forceinline__ uint32_t smem_u32(const void* p) {
    uint32_t a;
    asm("{ .reg .u64 t; cvta.to.shared.u64 t, %1; cvt.u32.u64 %0, t; }" : "=r"(a) : "l"(p));
    return a;
}
__device__ __forceinline__ void cpa16(uint32_t dst, const void* src, uint32_t srcsz) {
    asm volatile("cp.async.cg.shared.global [%0], [%1], 16, %2;"
                 :: "r"(dst), "l"(src), "r"(srcsz) : "memory");
}
#define CP_COMMIT() asm volatile("cp.async.commit_group;" ::: "memory")
#define CP_WAIT3()  asm volatile("cp.async.wait_group 3;" ::: "memory")

__device__ __forceinline__ void ldsm4(uint32_t& r0, uint32_t& r1, uint32_t& r2, uint32_t& r3,
                                      uint32_t addr) {
    asm volatile("ldmatrix.sync.aligned.m8n8.x4.shared.b16 {%0,%1,%2,%3}, [%4];"
                 : "=r"(r0), "=r"(r1), "=r"(r2), "=r"(r3) : "r"(addr));
}
__device__ __forceinline__ void mma_f16(float* c,
                                        uint32_t a0, uint32_t a1, uint32_t a2, uint32_t a3,
                                        uint32_t b0, uint32_t b1) {
    asm volatile(
        "mma.sync.aligned.m16n8k16.row.col.f32.f16.f16.f32 "
        "{%0,%1,%2,%3}, {%4,%5,%6,%7}, {%8,%9}, {%0,%1,%2,%3};"
        : "+f"(c[0]), "+f"(c[1]), "+f"(c[2]), "+f"(c[3])
        : "r"(a0), "r"(a1), "r"(a2), "r"(a3), "r"(b0), "r"(b1));
}

// ---------------- smem geometry ---------------------------------------------
#define ASTRB    144
#define A_BYTES  (128 * ASTRB)            // 18432
#define B_BYTES  (256 * ASTRB)            // 36864
#define STAGE_B  (A_BYTES + B_BYTES)      // 55296
#define SMEM_DYN (4 * STAGE_B)            // 221184, 4-stage pipeline
#define EPI_STR  264                      // fp32 epilogue stage stride

// ---------------- kernel 0: convert weights to fp16 (+ zero counters) -------
__global__ __launch_bounds__(256) void cvt_weights(
    const float4* __restrict__ s12, const float4* __restrict__ s3,
    const float4* __restrict__ e12, const float4* __restrict__ e3)
{
    if (blockIdx.x == 0 && threadIdx.x < NE) {
        g_cnt[threadIdx.x] = 0;
        g_cur[threadIdx.x] = 0;
    }
    const int N1 = 2 * HID * D_IN / 4;
    const int N2 = LLM * HID / 4;
    const int N3 = NE * 2 * HID * D_IN / 4;
    const int N4 = NE * LLM * HID / 4;
    const int total = N1 + N2 + N3 + N4;
    for (int i = blockIdx.x * blockDim.x + threadIdx.x; i < total;
         i += gridDim.x * blockDim.x) {
        float4 v; __half2* dst;
        int j = i;
        if (j < N1)              { v = s12[j]; dst = (__half2*)g_w12s + 2 * j; }
        else if ((j -= N1) < N2) { v = s3[j];  dst = (__half2*)g_w3s  + 2 * j; }
        else if ((j -= N2) < N3) { v = e12[j]; dst = (__half2*)g_w12e + 2 * j; }
        else { j -= N3;           v = e3[j];  dst = (__half2*)g_w3e  + 2 * j; }
        dst[0] = __floats2half2_rn(v.x, v.y);
        dst[1] = __floats2half2_rn(v.z, v.w);
    }
}

// ---------------- kernel 1: fused LN_pre + router ----------------------------
// 64 tokens/block, 188 blocks. Warp owns a token: x row in regs (fp32),
// butterfly mean/var, LN in regs, fp16 g_nx store, 8 expert dots vs smem rw.
__global__ __launch_bounds__(256) void ln_router_kernel(
    const float* __restrict__ x,
    const float* __restrict__ lng, const float* __restrict__ lnb,
    const float* __restrict__ rw,  const float* __restrict__ rb)
{
    extern __shared__ __align__(16) char smem[];
    float* s_rw = (float*)smem;                 // [NE][D_IN] fp32 = 80KB
    __shared__ int s_cnt[NE];
    int tid = threadIdx.x;
    if (tid < NE) s_cnt[tid] = 0;
    for (int i = tid; i < NE * D_IN / 4; i += 256)
        ((float4*)s_rw)[i] = ((const float4*)rw)[i];
    __syncthreads();

    int wid = tid >> 5, lane = tid & 31;
    for (int it = 0; it < 8; it++) {
        int t = blockIdx.x * 64 + wid * 8 + it;
        if (t >= T_TOK) break;
        const float2* row = (const float2*)(x + (size_t)t * D_IN);
        float2 h[40];
        float sum = 0.f, sq = 0.f;
        #pragma unroll
        for (int j = 0; j < 40; j++) {
            h[j] = row[lane + j * 32];
            sum += h[j].x + h[j].y;
            sq  += h[j].x * h[j].x + h[j].y * h[j].y;
        }
        #pragma unroll
        for (int o = 16; o > 0; o >>= 1) {
            sum += __shfl_xor_sync(0xFFFFFFFFu, sum, o);
            sq  += __shfl_xor_sync(0xFFFFFFFFu, sq,  o);
        }
        float m = sum * (1.f / D_IN);
        float var = sq * (1.f / D_IN) - m * m;
        float rinv = rsqrtf(var + 1e-6f);

        __half2* nxr = (__half2*)(g_nx + (size_t)t * D_IN);
        #pragma unroll
        for (int j = 0; j < 40; j++) {
            float2 gv = ((const float2*)lng)[lane + j * 32];
            float2 bv = ((const float2*)lnb)[lane + j * 32];
            h[j].x = (h[j].x - m) * rinv * gv.x + bv.x;
            h[j].y = (h[j].y - m) * rinv * gv.y + bv.y;
            nxr[lane + j * 32] = __floats2half2_rn(h[j].x, h[j].y);
        }

        float lg[NE];
        #pragma unroll
        for (int e = 0; e < NE; e++) {
            const float2* w2 = (const float2*)(s_rw + e * D_IN);
            float acc = 0.f;
            #pragma unroll
            for (int j = 0; j < 40; j++) {
                float2 wv = w2[lane + j * 32];
                acc = fmaf(h[j].x, wv.x, acc);
                acc = fmaf(h[j].y, wv.y, acc);
            }
            #pragma unroll
            for (int o = 16; o > 0; o >>= 1)
                acc += __shfl_down_sync(0xFFFFFFFFu, acc, o);
            lg[e] = acc;
        }
        if (lane == 0) {
            float p[NE];
            float mx = lg[0] + rb[0];
            #pragma unroll
            for (int e = 0; e < NE; e++) { p[e] = lg[e] + rb[e]; mx = fmaxf(mx, p[e]); }
            float se = 0.f;
            #pragma unroll
            for (int e = 0; e < NE; e++) { p[e] = __expf(p[e] - mx); se += p[e]; }
            float rse = 1.f / se;
            #pragma unroll
            for (int e = 0; e < NE; e++) p[e] *= rse;
            int i0 = 0;
            #pragma unroll
            for (int e = 1; e < NE; e++) if (p[e] > p[i0]) i0 = e;
            int i1 = (i0 == 0) ? 1 : 0;
            #pragma unroll
            for (int e = 0; e < NE; e++) if (e != i0 && p[e] > p[i1]) i1 = e;
            float s2 = p[i0] + p[i1] + 1e-20f;
            g_idx[2 * t + 0] = i0; g_w[2 * t + 0] = p[i0] / s2;
            g_idx[2 * t + 1] = i1; g_w[2 * t + 1] = p[i1] / s2;
            atomicAdd(&s_cnt[i0], 1);
            atomicAdd(&s_cnt[i1], 1);
        }
    }
    __syncthreads();
    if (tid < NE && s_cnt[tid]) atomicAdd(&g_cnt[tid], s_cnt[tid]);
}

// ---------------- kernel 2/3: scan + permutation (aggregated atomics) -------
__global__ void scan_kernel() {
    if (threadIdx.x == 0) {
        int o = 0;
        for (int e = 0; e < NE; e++) { g_off[e] = o; o += g_cnt[e]; }
        g_off[NE] = o;
    }
}
__global__ __launch_bounds__(256) void build_kernel() {
    __shared__ int s_cur[NE], s_base[NE];
    int tid = threadIdx.x;
    if (tid < NE) s_cur[tid] = 0;
    __syncthreads();
    int t = blockIdx.x * 256 + tid;
    int e2[2], lp[2];
    if (t < T_TOK) {
        #pragma unroll
        for (int k = 0; k < NTOP; k++) {
            e2[k] = g_idx[2 * t + k];
            lp[k] = atomicAdd(&s_cur[e2[k]], 1);
        }
    }
    __syncthreads();
    if (tid < NE) s_base[tid] = s_cur[tid] ? atomicAdd(&g_cur[tid], s_cur[tid]) : 0;
    __syncthreads();
    if (t < T_TOK) {
        #pragma unroll
        for (int k = 0; k < NTOP; k++) {
            int p = g_off[e2[k]] + s_base[e2[k]] + lp[k];
            g_perm[p]  = t;
            g_permw[p] = g_w[2 * t + k];
            g_pos[2 * t + k] = p;
        }
    }
}

// ============================================================================
// fp16 mma core: CTA 128x256, BK=64, 512 threads, 16 warps (4x4), warp 32x64
// ============================================================================
#define GEMM_FRAGS                                                            \
    const int lane = threadIdx.x & 31, wid = threadIdx.x >> 5;                \
    const int wm = (wid >> 2) * 32, wn = (wid & 3) * 64;                      \
    const int l16 = lane & 15, lh = lane >> 4;                                \
    const int bg = lane >> 3;                                                 \
    const int b_row = ((bg & 1) << 3) + (lane & 7), b_ch = bg >> 1;

#define LOAD_FRAGS(A, B, abase, bbase, step)                                  \
    _Pragma("unroll")                                                         \
    for (int mf = 0; mf < 2; mf++)                                            \
        ldsm4((A)[mf][0], (A)[mf][1], (A)[mf][2], (A)[mf][3],                 \
              (abase) + (wm + mf * 16 + l16) * ASTRB + ((step) * 2 + lh) * 16); \
    _Pragma("unroll")                                                         \
    for (int nb = 0; nb < 4; nb++)                                            \
        ldsm4((B)[nb][0], (B)[nb][1], (B)[nb][2], (B)[nb][3],                 \
              (bbase) + (wn + nb * 16 + b_row) * ASTRB + ((step) * 2 + b_ch) * 16);

#define MMA_FRAGS(A, B)                                                       \
    _Pragma("unroll")                                                         \
    for (int mf = 0; mf < 2; mf++)                                            \
        _Pragma("unroll")                                                     \
        for (int nb = 0; nb < 4; nb++) {                                      \
            mma_f16(acc[mf][2 * nb],     (A)[mf][0], (A)[mf][1], (A)[mf][2], (A)[mf][3], (B)[nb][0], (B)[nb][2]); \
            mma_f16(acc[mf][2 * nb + 1], (A)[mf][0], (A)[mf][1], (A)[mf][2], (A)[mf][3], (B)[nb][1], (B)[nb][3]); \
        }

#define GEMM_MAINLOOP(NK)                                                     \
    uint32_t af[2][4], bf[4][4];                                              \
    for (int kt = 0; kt < (NK); kt++) {                                       \
        CP_WAIT3();                                                           \
        __syncthreads();                                                      \
        uint32_t abase = sbase + (kt & 3) * STAGE_B;                          \
        uint32_t bbase = abase + A_BYTES;                                     \
        if (kt + 3 < (NK)) fill((kt + 3) & 3, (kt + 3) * 64);                 \
        else CP_COMMIT();                                                     \
        _Pragma("unroll")                                                     \
        for (int step = 0; step < 4; step++) {                                \
            LOAD_FRAGS(af, bf, abase, bbase, step)                            \
            MMA_FRAGS(af, bf)                                                 \
        }                                                                     \
    }

#define GEMM_EPI_STAGE(st)                                                    \
    {                                                                         \
        const int cg = lane >> 2, ct = lane & 3;                              \
        _Pragma("unroll")                                                     \
        for (int mf = 0; mf < 2; mf++) {                                      \
            int row = wm + mf * 16 + cg;                                      \
            _Pragma("unroll")                                                 \
            for (int nf = 0; nf < 8; nf++) {                                  \
                int col = wn + nf * 8 + ct * 2;                               \
                *(float2*)((st) + row * EPI_STR + col)       = make_float2(acc[mf][nf][0], acc[mf][nf][1]); \
                *(float2*)((st) + (row + 8) * EPI_STR + col) = make_float2(acc[mf][nf][2], acc[mf][nf][3]); \
            }                                                                 \
        }                                                                     \
    }

// ============================================================================
// kernel 4: GEMM w12 + fused SwiGLU, merged shared(z=0)/expert(z=1..8)
// ============================================================================
__global__ __launch_bounds__(512, 1) void gemm12_mma()
{
    const int z = blockIdx.z;
    int rowStart, nrows;
    const __half* W;
    if (z == 0) {
        rowStart = blockIdx.y * 128;
        if (rowStart >= T_TOK) return;
        nrows = min(128, T_TOK - rowStart);
        W = g_w12s;
    } else {
        int e = z - 1;
        int re = g_off[e + 1];
        rowStart = g_off[e] + blockIdx.y * 128;
        if (rowStart >= re) return;
        nrows = min(128, re - rowStart);
        W = g_w12e + (size_t)e * (2 * HID) * D_IN;
    }
    const int colBase = blockIdx.x * 128;   // act column tile

    extern __shared__ __align__(16) char smem[];
    __shared__ int s_perm[128];
    const uint32_t sbase = smem_u32(smem);
    const int tid = threadIdx.x;

    if (z && tid < 128)
        s_perm[tid] = (tid < nrows) ? g_perm[rowStart + tid] : 0;
    __syncthreads();

    // A: 512 threads cover 128 rows x 4 chunks of 32B
    const int arow = tid >> 2;
    const uint32_t avalid = (arow < nrows) ? 16 : 0;
    const __half* srcA = (z ? (g_nx + (size_t)s_perm[arow] * D_IN)
                            : (g_nx + (size_t)(rowStart + min(arow, nrows - 1)) * D_IN))
                         + (tid & 3) * 16;
    // B: 512 threads cover 256 rows x 2 chunks of 64B
    const int brow = tid >> 1;
    const int wrow = (brow < 128) ? (colBase + brow) : (HID + colBase + (brow - 128));
    const __half* srcB = W + (size_t)wrow * D_IN + (tid & 1) * 32;
    const uint32_t adst0 = sbase + arow * ASTRB + (tid & 3) * 32;
    const uint32_t bdst0 = sbase + A_BYTES + brow * ASTRB + (tid & 1) * 64;

    auto fill = [&](int s, int k0) {
        uint32_t ad = adst0 + s * STAGE_B;
        #pragma unroll
        for (int j = 0; j < 2; j++) cpa16(ad + j * 16, srcA + k0 + j * 8, avalid);
        uint32_t bd = bdst0 + s * STAGE_B;
        #pragma unroll
        for (int j = 0; j < 4; j++) cpa16(bd + j * 16, srcB + k0 + j * 8, 16);
        CP_COMMIT();
    };

    fill(0, 0); fill(1, 64); fill(2, 128);

    float acc[2][8][4] = {};
    GEMM_FRAGS
    GEMM_MAINLOOP(D_IN / 64)
    __syncthreads();

    float* st = (float*)smem;   // [128][EPI_STR]
    GEMM_EPI_STAGE(st)
    __syncthreads();

    __half* Out = z ? g_eact : g_act;
    #pragma unroll
    for (int i = 0; i < 8; i++) {
        int f = tid + i * 512;
        int r = f >> 5, c4 = f & 31;            // 32 x 4-half chunks = 128 cols
        if (r < nrows) {
            float4 gg = *(float4*)(st + r * EPI_STR + c4 * 4);
            float4 vv = *(float4*)(st + r * EPI_STR + 128 + c4 * 4);
            __half2 h0 = __floats2half2_rn(gg.x / (1.f + __expf(-gg.x)) * vv.x,
                                           gg.y / (1.f + __expf(-gg.y)) * vv.y);
            __half2 h1 = __floats2half2_rn(gg.z / (1.f + __expf(-gg.z)) * vv.z,
                                           gg.w / (1.f + __expf(-gg.w)) * vv.w);
            uint32_t u0 = *(uint32_t*)&h0, u1 = *(uint32_t*)&h1;
            *(uint2*)(Out + (size_t)(rowStart + r) * HID + colBase + c4 * 4) =
                make_uint2(u0, u1);
        }
    }
}

// ============================================================================
// kernel 5: GEMM w3 (+ fused routing weight), merged z, K=512, fp16 output
// ============================================================================
__global__ __launch_bounds__(512, 1) void gemm3_mma()
{
    const int z = blockIdx.z;
    int rowStart, nrows;
    const __half* W;
    if (z == 0) {
        rowStart = blockIdx.y * 128;
        if (rowStart >= T_TOK) return;
        nrows = min(128, T_TOK - rowStart);
        W = g_w3s;
    } else {
        int e = z - 1;
        int re = g_off[e + 1];
        rowStart = g_off[e] + blockIdx.y * 128;
        if (rowStart >= re) return;
        nrows = min(128, re - rowStart);
        W = g_w3e + (size_t)e * LLM * HID;
    }
    const int colBase = blockIdx.x * 256;
    const __half* Act = z ? g_eact : g_act;

    extern __shared__ __align__(16) char smem[];
    const uint32_t sbase = smem_u32(smem);
    const int tid = threadIdx.x;

    const int arow = tid >> 2;
    const uint32_t avalid = (arow < nrows) ? 16 : 0;
    const __half* srcA = Act + (size_t)(rowStart + min(arow, nrows - 1)) * HID + (tid & 3) * 16;
    const int brow = tid >> 1;
    const __half* srcB = W + (size_t)(colBase + brow) * HID + (tid & 1) * 32;
    const uint32_t adst0 = sbase + arow * ASTRB + (tid & 3) * 32;
    const uint32_t bdst0 = sbase + A_BYTES + brow * ASTRB + (tid & 1) * 64;

    auto fill = [&](int s, int k0) {
        uint32_t ad = adst0 + s * STAGE_B;
        #pragma unroll
        for (int j = 0; j < 2; j++) cpa16(ad + j * 16, srcA + k0 + j * 8, avalid);
        uint32_t bd = bdst0 + s * STAGE_B;
        #pragma unroll
        for (int j = 0; j < 4; j++) cpa16(bd + j * 16, srcB + k0 + j * 8, 16);
        CP_COMMIT();
    };

    fill(0, 0); fill(1, 64); fill(2, 128);

    float acc[2][8][4] = {};
    GEMM_FRAGS
    GEMM_MAINLOOP(HID / 64)
    __syncthreads();

    float* st = (float*)smem;   // [128][EPI_STR]
    GEMM_EPI_STAGE(st)
    __syncthreads();

    __half* Out = z ? g_eo : g_shared;
    #pragma unroll
    for (int i = 0; i < 8; i++) {
        int f = tid + i * 512;
        int r = f >> 5, ch = f & 31;            // 32 chunks of 8 halfs = 256 cols
        if (r < nrows) {
            float sc = z ? g_permw[rowStart + r] : 1.f;
            const float* s0 = st + r * EPI_STR + ch * 8;
            __half2 h0 = __floats2half2_rn(sc * s0[0], sc * s0[1]);
            __half2 h1 = __floats2half2_rn(sc * s0[2], sc * s0[3]);
            __half2 h2 = __floats2half2_rn(sc * s0[4], sc * s0[5]);
            __half2 h3 = __floats2half2_rn(sc * s0[6], sc * s0[7]);
            uint4 u;
            u.x = *(uint32_t*)&h0; u.y = *(uint32_t*)&h1;
            u.z = *(uint32_t*)&h2; u.w = *(uint32_t*)&h3;
            *(uint4*)(Out + (size_t)(rowStart + r) * LLM + colBase + ch * 8) = u;
        }
    }
}

// ---------------- kernel 6: combine + LN_post (fp16 inputs) ------------------
__device__ __forceinline__ void blockReduce2(float& sum, float& sq) {
    __shared__ float ss[8], sv[8];
    #pragma unroll
    for (int o = 16; o > 0; o >>= 1) {
        sum += __shfl_down_sync(0xFFFFFFFFu, sum, o);
        sq  += __shfl_down_sync(0xFFFFFFFFu, sq,  o);
    }
    int w = threadIdx.x >> 5, l = threadIdx.x & 31;
    if (l == 0) { ss[w] = sum; sv[w] = sq; }
    __syncthreads();
    if (w == 0) {
        sum = (l < 8) ? ss[l] : 0.f;
        sq  = (l < 8) ? sv[l] : 0.f;
        #pragma unroll
        for (int o = 4; o > 0; o >>= 1) {
            sum += __shfl_down_sync(0xFFFFFFFFu, sum, o);
            sq  += __shfl_down_sync(0xFFFFFFFFu, sq,  o);
        }
        if (l == 0) { ss[0] = sum; sv[0] = sq; }
    }
    __syncthreads();
    sum = ss[0]; sq = sv[0];
}

__global__ __launch_bounds__(256) void ln_post_kernel(
    const float* __restrict__ lng, const float* __restrict__ lnb,
    float* __restrict__ out)
{
    int t = blockIdx.x;
    int tid = threadIdx.x;
    int p0 = g_pos[2 * t + 0], p1 = g_pos[2 * t + 1];
    const __half2* sh = (const __half2*)(g_shared + (size_t)t * LLM);
    const __half2* e0 = (const __half2*)(g_eo + (size_t)p0 * LLM);
    const __half2* e1 = (const __half2*)(g_eo + (size_t)p1 * LLM);
    float2 v[4];
    float sum = 0.f, sq = 0.f;
    #pragma unroll
    for (int i = 0; i < 4; i++) {
        int j = tid + i * 256;          // half2 index, j < 1024
        float2 a = __half22float2(sh[j]);
        float2 b = __half22float2(e0[j]);
        float2 c = __half22float2(e1[j]);
        float2 val = make_float2(a.x + b.x + c.x, a.y + b.y + c.y);
        v[i] = val;
        sum += val.x + val.y;
        sq += val.x * val.x + val.y * val.y;
    }
    blockReduce2(sum, sq);
    float m = sum * (1.f / LLM);
    float var = sq * (1.f / LLM) - m * m;
    float rinv = rsqrtf(var + 1e-6f);
    float* orow = out + (size_t)t * LLM;
    #pragma unroll
    for (int i = 0; i < 4; i++) {
        int j = tid + i * 256;
        float2 gv = ((const float2*)lng)[j];
        float2 bv = ((const float2*)lnb)[j];
        float2 o;
        o.x = (v[i].x - m) * rinv * gv.x + bv.x;
        o.y = (v[i].y - m) * rinv * gv.y + bv.y;
        *(float2*)(orow + 2 * j) = o;
    }
}

// ---------------- launcher ----------------------------------------------------
extern "C" void kernel_launch(void* const* d_in, const int* in_sizes, int n_in,
                              void* d_out, int out_size)
{
    const float* x           = (const float*)d_in[0];
    const float* ln_pre_g    = (const float*)d_in[1];
    const float* ln_pre_b    = (const float*)d_in[2];
    const float* router_w    = (const float*)d_in[3];
    const float* router_b    = (const float*)d_in[4];
    const float* shared_w12  = (const float*)d_in[5];
    const float* shared_w3   = (const float*)d_in[6];
    const float* experts_w12 = (const float*)d_in[7];
    const float* experts_w3  = (const float*)d_in[8];
    const float* ln_post_g   = (const float*)d_in[9];
    const float* ln_post_b   = (const float*)d_in[10];
    float* out = (float*)d_out;

    const int RW_SMEM = NE * D_IN * 4;  // 80 KB
    cudaFuncSetAttribute(gemm12_mma, cudaFuncAttributeMaxDynamicSharedMemorySize, SMEM_DYN);
    cudaFuncSetAttribute(gemm3_mma,  cudaFuncAttributeMaxDynamicSharedMemorySize, SMEM_DYN);
    cudaFuncSetAttribute(ln_router_kernel, cudaFuncAttributeMaxDynamicSharedMemorySize, RW_SMEM);

    cvt_weights<<<4096, 256>>>((const float4*)shared_w12, (const float4*)shared_w3,
                               (const float4*)experts_w12, (const float4*)experts_w3);
    ln_router_kernel<<<(T_TOK + 63) / 64, 256, RW_SMEM>>>(x, ln_pre_g, ln_pre_b,
                                                          router_w, router_b);
    scan_kernel<<<1, 32>>>();
    build_kernel<<<(T_TOK + 255) / 256, 256>>>();

    const int MT = (T_TOK + 127) / 128;   // 94 (also covers worst-case expert)
    gemm12_mma<<<dim3(HID / 128, MT, NE + 1), 512, SMEM_DYN>>>();
    gemm3_mma <<<dim3(LLM / 256, MT, NE + 1), 512, SMEM_DYN>>>();

    ln_post_kernel<<<T_TOK, 256>>>(ln_post_g, ln_post_b, out);
}